// round 8
// baseline (speedup 1.0000x reference)
#include <cuda_runtime.h>
#include <cuda_bf16.h>
#include <math_constants.h>
#include <cstdint>

#define NS 100000
#define ND 100000
#define NE 1600000
#define DIN 256
#define NH 4
#define DH 32
#define HD 128          // NH * DH
#define NEG_SLOPE 0.2f
#define NBLK ((ND + 255) / 256)   // 391 scan blocks

// ---------------- scratch (device globals; no allocs allowed) ----------------
__device__ __align__(16) float g_fs[(size_t)NS * HD];    // 51.2 MB projected src feats
__device__ __align__(16) float g_esrc[NS * NH];
__device__ __align__(16) float g_edst[ND * NH];
__device__ __align__(16) float g_e[(size_t)NE * NH];     // edge logits (post leaky-relu)
__device__ __align__(16) float g_vdst[DIN * NH];         // folded w_dst @ attn_dst
__device__ int  g_cnt[ND];
__device__ int  g_wpos[ND];
__device__ int  g_base[ND];
__device__ int  g_bsum[NBLK];
__device__ int  g_boff[NBLK];
__device__ __align__(8) int2 g_sorted[NE];   // {edge_id, src} sorted by dst

// ---------------- K0: init counters ----------------
__global__ void init_kernel() {
    int tix = blockIdx.x * blockDim.x + threadIdx.x;
    if (tix < ND) { g_cnt[tix] = 0; g_wpos[tix] = 0; }
}

// ---------------- K1: fs = feat_src @ w_src via mma.sync bf16x3 -------------
// K-extension: A' = [Ahi | Alo | Ahi], B' = [Bhi ; Bhi ; Blo]  (K'=768)
// => fp32 acc of hi*hi + lo*hi + hi*lo  (dropped lo*lo term ~2^-18).
// CTA tile 128x128, 8 warps, warp tile 32x64, 16 chunks of 48 extended-K.
#define AS_STR 56
#define BS_STR 56

__device__ __forceinline__ void mma16816(float* c, const uint32_t* a, const uint32_t* b) {
    asm volatile("mma.sync.aligned.m16n8k16.row.col.f32.bf16.bf16.f32 "
                 "{%0,%1,%2,%3}, {%4,%5,%6,%7}, {%8,%9}, {%0,%1,%2,%3};"
                 : "+f"(c[0]), "+f"(c[1]), "+f"(c[2]), "+f"(c[3])
                 : "r"(a[0]), "r"(a[1]), "r"(a[2]), "r"(a[3]), "r"(b[0]), "r"(b[1]));
}

__global__ __launch_bounds__(256, 2) void gemm_mma_kernel(
    const float* __restrict__ A,   // [NS, 256]
    const float* __restrict__ B)   // [256, 128]
{
    __shared__ __nv_bfloat16 As[128][AS_STR];   // cols 0-15 hi | 16-31 lo | 32-47 hi
    __shared__ __nv_bfloat16 Bs[128][BS_STR];   // n-major: 0-15 hi | 16-31 hi | 32-47 lo

    const int tid  = threadIdx.x;
    const int wid  = tid >> 5;
    const int lane = tid & 31;
    const int grp  = lane >> 2;             // 0..7
    const int quad = lane & 3;              // 0..3
    const int mwarp = (wid & 3) * 32;       // warp m-offset
    const int nwarp = (wid >> 2) * 64;      // warp n-offset
    const int row0  = blockIdx.x * 128;

    const int ar  = tid >> 1, acb = (tid & 1) * 8;
    const int bkr = tid & 15, bn0 = (tid >> 4) * 8;

    float acc[2][8][4];
#pragma unroll
    for (int mf = 0; mf < 2; mf++)
#pragma unroll
        for (int nf = 0; nf < 8; nf++)
#pragma unroll
            for (int q = 0; q < 4; q++) acc[mf][nf][q] = 0.0f;

    // prefetch chunk 0
    float4 pa0, pa1, pb0, pb1;
    {
        const int gr = row0 + ar;
        if (gr < NS) {
            pa0 = *(const float4*)(A + (size_t)gr * DIN + acb);
            pa1 = *(const float4*)(A + (size_t)gr * DIN + acb + 4);
        } else {
            pa0 = make_float4(0.f, 0.f, 0.f, 0.f);
            pa1 = make_float4(0.f, 0.f, 0.f, 0.f);
        }
        pb0 = *(const float4*)(B + (size_t)bkr * HD + bn0);
        pb1 = *(const float4*)(B + (size_t)bkr * HD + bn0 + 4);
    }

    for (int ch = 0; ch < 16; ch++) {
        // ---- convert + store current chunk to smem ----
        {
            const float av[8] = {pa0.x, pa0.y, pa0.z, pa0.w, pa1.x, pa1.y, pa1.z, pa1.w};
            uint32_t hw[4], lw[4];
#pragma unroll
            for (int p = 0; p < 4; p++) {
                __nv_bfloat162 h = __floats2bfloat162_rn(av[2*p], av[2*p+1]);
                float2 hf = __bfloat1622float2(h);
                __nv_bfloat162 l = __floats2bfloat162_rn(av[2*p] - hf.x, av[2*p+1] - hf.y);
                hw[p] = *(uint32_t*)&h;
                lw[p] = *(uint32_t*)&l;
            }
            uint32_t* ra = (uint32_t*)&As[ar][acb];
            uint32_t* rb = (uint32_t*)&As[ar][acb + 16];
            uint32_t* rc = (uint32_t*)&As[ar][acb + 32];
#pragma unroll
            for (int p = 0; p < 4; p++) { ra[p] = hw[p]; rb[p] = lw[p]; rc[p] = hw[p]; }

            const float bv[8] = {pb0.x, pb0.y, pb0.z, pb0.w, pb1.x, pb1.y, pb1.z, pb1.w};
#pragma unroll
            for (int j = 0; j < 8; j++) {
                __nv_bfloat16 h = __float2bfloat16(bv[j]);
                __nv_bfloat16 l = __float2bfloat16(bv[j] - __bfloat162float(h));
                Bs[bn0 + j][bkr]      = h;
                Bs[bn0 + j][16 + bkr] = h;
                Bs[bn0 + j][32 + bkr] = l;
            }
        }
        __syncthreads();

        // ---- prefetch next chunk (LDG latency hidden under MMAs) ----
        if (ch + 1 < 16) {
            const int k0 = (ch + 1) * 16;
            const int gr = row0 + ar;
            if (gr < NS) {
                pa0 = *(const float4*)(A + (size_t)gr * DIN + k0 + acb);
                pa1 = *(const float4*)(A + (size_t)gr * DIN + k0 + acb + 4);
            } else {
                pa0 = make_float4(0.f, 0.f, 0.f, 0.f);
                pa1 = make_float4(0.f, 0.f, 0.f, 0.f);
            }
            pb0 = *(const float4*)(B + (size_t)(k0 + bkr) * HD + bn0);
            pb1 = *(const float4*)(B + (size_t)(k0 + bkr) * HD + bn0 + 4);
        }

        // ---- 3 x 16 MMAs over the 48 extended-K columns ----
#pragma unroll
        for (int kf = 0; kf < 3; kf++) {
            const int kO = kf * 16;
            uint32_t af[2][4];
#pragma unroll
            for (int mf = 0; mf < 2; mf++) {
                const int r = mwarp + mf * 16 + grp;
                af[mf][0] = *(uint32_t*)&As[r][kO + quad * 2];
                af[mf][1] = *(uint32_t*)&As[r + 8][kO + quad * 2];
                af[mf][2] = *(uint32_t*)&As[r][kO + quad * 2 + 8];
                af[mf][3] = *(uint32_t*)&As[r + 8][kO + quad * 2 + 8];
            }
            uint32_t bfr[8][2];
#pragma unroll
            for (int nf = 0; nf < 8; nf++) {
                const int n = nwarp + nf * 8 + grp;
                bfr[nf][0] = *(uint32_t*)&Bs[n][kO + quad * 2];
                bfr[nf][1] = *(uint32_t*)&Bs[n][kO + quad * 2 + 8];
            }
#pragma unroll
            for (int mf = 0; mf < 2; mf++)
#pragma unroll
                for (int nf = 0; nf < 8; nf++)
                    mma16816(acc[mf][nf], af[mf], bfr[nf]);
        }
        __syncthreads();
    }

    // ---- writeback ----
#pragma unroll
    for (int mf = 0; mf < 2; mf++) {
        const int r0w = row0 + mwarp + mf * 16 + grp;
        const int r1w = r0w + 8;
#pragma unroll
        for (int nf = 0; nf < 8; nf++) {
            const int col = nwarp + nf * 8 + quad * 2;
            if (r0w < NS) {
                float2 v = make_float2(acc[mf][nf][0], acc[mf][nf][1]);
                *(float2*)(g_fs + (size_t)r0w * HD + col) = v;
            }
            if (r1w < NS) {
                float2 v = make_float2(acc[mf][nf][2], acc[mf][nf][3]);
                *(float2*)(g_fs + (size_t)r1w * HD + col) = v;
            }
        }
    }
}

// ---------------- K2a: fold v_dst[k][h] = sum_j w_dst[k,h*32+j]*attn[h,j] ---
__global__ void vdst_kernel(const float* __restrict__ wd,
                            const float* __restrict__ attn)
{
    int t = blockIdx.x * blockDim.x + threadIdx.x;
    if (t >= DIN * NH) return;
    int k = t >> 2, h = t & 3;
    float s = 0.0f;
#pragma unroll
    for (int j = 0; j < DH; j++)
        s += wd[(size_t)k * HD + h * DH + j] * attn[h * (2 * DH) + j];
    g_vdst[k * NH + h] = s;
}

// ---------------- K2b: e_dst = feat_dst @ v_dst (warp/node, float4 MLP) -----
__global__ __launch_bounds__(256) void edst_kernel(const float* __restrict__ fd)
{
    __shared__ float4 vs4[DIN];
    int tid = threadIdx.x;
    for (int i = tid; i < DIN; i += 256) vs4[i] = *(const float4*)&g_vdst[i * NH];
    __syncthreads();
    int warp = tid >> 5, lane = tid & 31;
    int n = blockIdx.x * 8 + warp;
    if (n >= ND) return;
    const float4* fr4 = (const float4*)(fd + (size_t)n * DIN);
    float4 x = fr4[lane];          // k = 4*lane .. +3
    float4 y = fr4[lane + 32];     // k = 128 + 4*lane .. +3
    float a0 = 0, a1 = 0, a2 = 0, a3 = 0;
    float fx[8] = {x.x, x.y, x.z, x.w, y.x, y.y, y.z, y.w};
#pragma unroll
    for (int j = 0; j < 8; j++) {
        int k = (j < 4) ? (4 * lane + j) : (128 + 4 * lane + (j - 4));
        float4 v = vs4[k];
        a0 += fx[j] * v.x; a1 += fx[j] * v.y; a2 += fx[j] * v.z; a3 += fx[j] * v.w;
    }
#pragma unroll
    for (int o = 16; o >= 1; o >>= 1) {
        a0 += __shfl_down_sync(0xffffffffu, a0, o);
        a1 += __shfl_down_sync(0xffffffffu, a1, o);
        a2 += __shfl_down_sync(0xffffffffu, a2, o);
        a3 += __shfl_down_sync(0xffffffffu, a3, o);
    }
    if (lane == 0) {
        g_edst[n * NH + 0] = a0;
        g_edst[n * NH + 1] = a1;
        g_edst[n * NH + 2] = a2;
        g_edst[n * NH + 3] = a3;
    }
}

// ---------------- K2c: e_src from fs (warp per node) ------------------------
__global__ __launch_bounds__(256) void esrc_kernel(const float* __restrict__ attn)
{
    int tid = threadIdx.x;
    int warp = tid >> 5, lane = tid & 31;
    int n = blockIdx.x * 8 + warp;
    if (n >= NS) return;
    int h = lane >> 3;
    int j = (lane & 7) * 4;
    float4 f = *(const float4*)&g_fs[(size_t)n * HD + lane * 4];
    const float* ar = attn + h * (2 * DH) + DH + j;
    float p = f.x * ar[0] + f.y * ar[1] + f.z * ar[2] + f.w * ar[3];
    p += __shfl_down_sync(0xffffffffu, p, 4, 8);
    p += __shfl_down_sync(0xffffffffu, p, 2, 8);
    p += __shfl_down_sync(0xffffffffu, p, 1, 8);
    if ((lane & 7) == 0) g_esrc[n * NH + h] = p;
}

// ---------------- K3: edge logits + leaky relu + dst histogram --------------
__global__ void edge_logits_kernel(const int* __restrict__ src,
                                   const int* __restrict__ dst)
{
    int i = blockIdx.x * blockDim.x + threadIdx.x;
    if (i >= NE) return;
    int s = src[i], d = dst[i];
    float4 es = *(const float4*)&g_esrc[(size_t)s * NH];
    float4 ed = *(const float4*)&g_edst[(size_t)d * NH];
    float4 e;
    e.x = es.x + ed.x; e.x = e.x > 0.f ? e.x : NEG_SLOPE * e.x;
    e.y = es.y + ed.y; e.y = e.y > 0.f ? e.y : NEG_SLOPE * e.y;
    e.z = es.z + ed.z; e.z = e.z > 0.f ? e.z : NEG_SLOPE * e.z;
    e.w = es.w + ed.w; e.w = e.w > 0.f ? e.w : NEG_SLOPE * e.w;
    *(float4*)&g_e[(size_t)i * NH] = e;
    atomicAdd(&g_cnt[d], 1);
}

// ---------------- K4a: per-block exclusive scan of g_cnt --------------------
__global__ __launch_bounds__(256) void scan_block_kernel()
{
    int t = threadIdx.x;
    int i = blockIdx.x * 256 + t;
    int c = (i < ND) ? g_cnt[i] : 0;
    int lane = t & 31, w = t >> 5;
    int inc = c;
#pragma unroll
    for (int o = 1; o < 32; o <<= 1) {
        int n = __shfl_up_sync(0xffffffffu, inc, o);
        if (lane >= o) inc += n;
    }
    __shared__ int ws[8];
    if (lane == 31) ws[w] = inc;
    __syncthreads();
    if (t < 8) {
        int v = ws[t];
        int inc2 = v;
#pragma unroll
        for (int o = 1; o < 8; o <<= 1) {
            int n = __shfl_up_sync(0x000000ffu, inc2, o);
            if (t >= o) inc2 += n;
        }
        ws[t] = inc2 - v;
    }
    __syncthreads();
    int excl = inc - c + ws[w];
    if (i < ND) g_base[i] = excl;
    if (t == 255) g_bsum[blockIdx.x] = excl + c;
}

// ---------------- K4b: scan the 391 block sums ------------------------------
__global__ __launch_bounds__(512) void scan_top_kernel()
{
    int t = threadIdx.x;
    int c = (t < NBLK) ? g_bsum[t] : 0;
    int lane = t & 31, w = t >> 5;
    int inc = c;
#pragma unroll
    for (int o = 1; o < 32; o <<= 1) {
        int n = __shfl_up_sync(0xffffffffu, inc, o);
        if (lane >= o) inc += n;
    }
    __shared__ int ws[16];
    if (lane == 31) ws[w] = inc;
    __syncthreads();
    if (t < 16) {
        int v = ws[t];
        int inc2 = v;
#pragma unroll
        for (int o = 1; o < 16; o <<= 1) {
            int n = __shfl_up_sync(0x0000ffffu, inc2, o);
            if (t >= o) inc2 += n;
        }
        ws[t] = inc2 - v;
    }
    __syncthreads();
    if (t < NBLK) g_boff[t] = inc - c + ws[w];
}

// ---------------- K5: scatter edges into dst-sorted order -------------------
__global__ void scatter_kernel(const int* __restrict__ src,
                               const int* __restrict__ dst)
{
    int i = blockIdx.x * blockDim.x + threadIdx.x;
    if (i >= NE) return;
    int d = dst[i];
    int s = src[i];
    int pos = atomicAdd(&g_wpos[d], 1);
    int slot = g_base[d] + g_boff[d >> 8] + pos;
    g_sorted[slot] = make_int2(i, s);
}

// ---------------- K6: warp-per-dst online-softmax aggregation ---------------
__global__ __launch_bounds__(256) void aggregate_kernel(float* __restrict__ out)
{
    int warp = threadIdx.x >> 5, lane = threadIdx.x & 31;
    int d = blockIdx.x * 8 + warp;
    if (d >= ND) return;
    int base = g_base[d] + g_boff[d >> 8];
    int cnt  = g_cnt[d];
    int h = lane >> 3;

    float m = -CUDART_INF_F;
    float denom = 0.0f;
    float4 acc = make_float4(0.f, 0.f, 0.f, 0.f);

    int2 es; float e; float4 f;
    if (cnt > 0) {
        es = g_sorted[base];
        e  = __ldg(&g_e[(size_t)es.x * NH + h]);
        f  = *(const float4*)&g_fs[(size_t)es.y * HD + lane * 4];
    }
    for (int j = 0; j < cnt; j++) {
        int2 es_n; float e_n; float4 f_n;
        if (j + 1 < cnt) {
            es_n = g_sorted[base + j + 1];
            e_n  = __ldg(&g_e[(size_t)es_n.x * NH + h]);
            f_n  = *(const float4*)&g_fs[(size_t)es_n.y * HD + lane * 4];
        }
        if (e > m) {
            float sc = __expf(m - e);
            m = e;
            denom = denom * sc + 1.0f;
            acc.x = acc.x * sc + f.x;
            acc.y = acc.y * sc + f.y;
            acc.z = acc.z * sc + f.z;
            acc.w = acc.w * sc + f.w;
        } else {
            float w = __expf(e - m);
            denom += w;
            acc.x += w * f.x;
            acc.y += w * f.y;
            acc.z += w * f.z;
            acc.w += w * f.w;
        }
        es = es_n; e = e_n; f = f_n;
    }
    float inv = (cnt > 0) ? 1.0f / denom : 0.0f;
    float4 o;
    o.x = fmaxf(acc.x * inv, 0.f);
    o.y = fmaxf(acc.y * inv, 0.f);
    o.z = fmaxf(acc.z * inv, 0.f);
    o.w = fmaxf(acc.w * inv, 0.f);
    *(float4*)(out + (size_t)d * HD + lane * 4) = o;
}

// ---------------- launch -----------------------------------------------------
extern "C" void kernel_launch(void* const* d_in, const int* in_sizes, int n_in,
                              void* d_out, int out_size)
{
    const float* feat_src = (const float*)d_in[0];
    const float* feat_dst = (const float*)d_in[1];
    const float* w_src    = (const float*)d_in[2];
    const float* w_dst    = (const float*)d_in[3];
    const float* attn     = (const float*)d_in[4];
    const int*   src_idx  = (const int*)d_in[5];
    const int*   dst_idx  = (const int*)d_in[6];
    float* out = (float*)d_out;

    init_kernel<<<(ND + 255) / 256, 256>>>();
    gemm_mma_kernel<<<(NS + 127) / 128, 256>>>(feat_src, w_src);
    vdst_kernel<<<(DIN * NH + 255) / 256, 256>>>(w_dst, attn);
    edst_kernel<<<(ND + 7) / 8, 256>>>(feat_dst);
    esrc_kernel<<<(NS + 7) / 8, 256>>>(attn);
    edge_logits_kernel<<<NE / 256, 256>>>(src_idx, dst_idx);
    scan_block_kernel<<<NBLK, 256>>>();
    scan_top_kernel<<<1, 512>>>();
    scatter_kernel<<<NE / 256, 256>>>(src_idx, dst_idx);
    aggregate_kernel<<<(ND + 7) / 8, 256>>>(out);
}

// round 10
// speedup vs baseline: 1.1089x; 1.1089x over previous
#include <cuda_runtime.h>
#include <cuda_bf16.h>
#include <math_constants.h>
#include <cstdint>

#define NS 100000
#define ND 100000
#define NE 1600000
#define DIN 256
#define NH 4
#define DH 32
#define HD 128          // NH * DH
#define NEG_SLOPE 0.2f
#define NBLK ((ND + 255) / 256)   // 391 scan blocks
#define NSP 100096                // NS padded to 128 (782 CTAs * 128)

// ---------------- scratch (device globals; no allocs allowed) ----------------
__device__ __align__(16) float g_fs[(size_t)NS * HD];    // 51.2 MB projected src feats
__device__ __align__(16) __nv_bfloat16 g_ahi[(size_t)NSP * DIN];  // A split hi
__device__ __align__(16) __nv_bfloat16 g_alo[(size_t)NSP * DIN];  // A split lo
__device__ __align__(16) __nv_bfloat16 g_bhi[HD * DIN];  // w_src split hi, n-major [128][256]
__device__ __align__(16) __nv_bfloat16 g_blo[HD * DIN];  // w_src split lo, n-major
__device__ __align__(16) float g_esrc[NS * NH];
__device__ __align__(16) float g_edst[ND * NH];
__device__ __align__(16) float g_e[(size_t)NE * NH];     // edge logits (post leaky-relu)
__device__ __align__(16) float g_vdst[DIN * NH];         // folded w_dst @ attn_dst
__device__ int  g_cnt[ND];
__device__ int  g_wpos[ND];
__device__ int  g_base[ND];
__device__ int  g_bsum[NBLK];
__device__ int  g_boff[NBLK];
__device__ __align__(8) int2 g_sorted[NE];   // {edge_id, src} sorted by dst

// ---------------- K0: init counters ----------------
__global__ void init_kernel() {
    int tix = blockIdx.x * blockDim.x + threadIdx.x;
    if (tix < ND) { g_cnt[tix] = 0; g_wpos[tix] = 0; }
}

// ---------------- P1: split A -> bf16 hi/lo ---------------------------------
__global__ __launch_bounds__(256) void convA_kernel(const float* __restrict__ A)
{
    size_t i = (size_t)blockIdx.x * blockDim.x + threadIdx.x;
    if (i >= (size_t)NS * (DIN / 4)) return;
    float4 v = ((const float4*)A)[i];
    __nv_bfloat162 h0 = __floats2bfloat162_rn(v.x, v.y);
    __nv_bfloat162 h1 = __floats2bfloat162_rn(v.z, v.w);
    float2 f0 = __bfloat1622float2(h0);
    float2 f1 = __bfloat1622float2(h1);
    __nv_bfloat162 l0 = __floats2bfloat162_rn(v.x - f0.x, v.y - f0.y);
    __nv_bfloat162 l1 = __floats2bfloat162_rn(v.z - f1.x, v.w - f1.y);
    ((uint2*)g_ahi)[i] = make_uint2(*(uint32_t*)&h0, *(uint32_t*)&h1);
    ((uint2*)g_alo)[i] = make_uint2(*(uint32_t*)&l0, *(uint32_t*)&l1);
}

// ---------------- P2: split B -> bf16 hi/lo, transposed to n-major ----------
__global__ void convB_kernel(const float* __restrict__ B)
{
    int i = blockIdx.x * blockDim.x + threadIdx.x;
    if (i >= DIN * HD) return;
    int k = i >> 7, n = i & 127;
    float v = B[i];
    __nv_bfloat16 h = __float2bfloat16(v);
    __nv_bfloat16 l = __float2bfloat16(v - __bfloat162float(h));
    g_bhi[n * DIN + k] = h;
    g_blo[n * DIN + k] = l;
}

// ---------------- K1: fs = A @ B via mma.sync bf16x3, cp.async pipeline -----
// Per CTA: 128x128 tile. 16 K-chunks of 16. Double-buffered 48KB static smem.
// Per chunk, 3 MMA passes: (Ahi,Bhi), (Alo,Bhi), (Ahi,Blo)   [lo*lo dropped]
#define KCH 16
#define SSTR 24      // bf16 stride; 12 words -> conflict-free frag loads

__device__ __forceinline__ void mma16816(float* c, const uint32_t* a, const uint32_t* b) {
    asm volatile("mma.sync.aligned.m16n8k16.row.col.f32.bf16.bf16.f32 "
                 "{%0,%1,%2,%3}, {%4,%5,%6,%7}, {%8,%9}, {%0,%1,%2,%3};"
                 : "+f"(c[0]), "+f"(c[1]), "+f"(c[2]), "+f"(c[3])
                 : "r"(a[0]), "r"(a[1]), "r"(a[2]), "r"(a[3]), "r"(b[0]), "r"(b[1]));
}
__device__ __forceinline__ uint32_t smem_u32(const void* p) {
    uint32_t a;
    asm("{ .reg .u64 t; cvta.to.shared.u64 t, %1; cvt.u32.u64 %0, t; }" : "=r"(a) : "l"(p));
    return a;
}
__device__ __forceinline__ void cpa16(uint32_t dst, const void* src) {
    asm volatile("cp.async.ca.shared.global [%0], [%1], 16;" :: "r"(dst), "l"(src));
}
#define CP_COMMIT() asm volatile("cp.async.commit_group;" ::: "memory")
#define CP_WAIT0()  asm volatile("cp.async.wait_group 0;" ::: "memory")

__global__ __launch_bounds__(256, 2) void gemm_mma_kernel()
{
    // [stage][array: Ahi,Alo,Bhi,Blo][row 0..127][SSTR]  = 49152 bytes
    // __align__(16) REQUIRED: cp.async 16B needs 16B-aligned smem destination.
    __shared__ __align__(16) __nv_bfloat16 S[2][4][128][SSTR];

    const int tid  = threadIdx.x;
    const int wid  = tid >> 5;
    const int lane = tid & 31;
    const int grp  = lane >> 2;
    const int quad = lane & 3;
    const int mwarp = (wid & 3) * 32;
    const int nwarp = (wid >> 2) * 64;
    const int row0  = blockIdx.x * 128;

    float acc[2][8][4];
#pragma unroll
    for (int mf = 0; mf < 2; mf++)
#pragma unroll
        for (int nf = 0; nf < 8; nf++)
#pragma unroll
            for (int q = 0; q < 4; q++) acc[mf][nf][q] = 0.0f;

    // copy assignment: 1024 x 16B per chunk, 4 per thread
    auto copy_chunk = [&](int ch, int stage) {
        const int k0 = ch * KCH;
#pragma unroll
        for (int i = 0; i < 4; i++) {
            int idx = i * 256 + tid;
            int arr = idx >> 8;
            int row = (idx >> 1) & 127;
            int seg = idx & 1;
            const __nv_bfloat16* sp;
            if (arr == 0)      sp = g_ahi + (size_t)(row0 + row) * DIN + k0 + seg * 8;
            else if (arr == 1) sp = g_alo + (size_t)(row0 + row) * DIN + k0 + seg * 8;
            else if (arr == 2) sp = g_bhi + (size_t)row * DIN + k0 + seg * 8;
            else               sp = g_blo + (size_t)row * DIN + k0 + seg * 8;
            cpa16(smem_u32(&S[stage][arr][row][seg * 8]), sp);
        }
    };

    copy_chunk(0, 0);
    CP_COMMIT();
    CP_WAIT0();
    __syncthreads();

    int buf = 0;
    for (int ch = 0; ch < DIN / KCH; ch++) {
        if (ch + 1 < DIN / KCH) {
            copy_chunk(ch + 1, buf ^ 1);
            CP_COMMIT();
        }

        // ---- fragment loads (conflict-free: 12*grp + quad covers 32 banks) ----
        uint32_t ah[2][4], al[2][4], bh[8][2], bl[8][2];
#pragma unroll
        for (int mf = 0; mf < 2; mf++) {
            const int r = mwarp + mf * 16 + grp;
            ah[mf][0] = *(uint32_t*)&S[buf][0][r][quad * 2];
            ah[mf][1] = *(uint32_t*)&S[buf][0][r + 8][quad * 2];
            ah[mf][2] = *(uint32_t*)&S[buf][0][r][quad * 2 + 8];
            ah[mf][3] = *(uint32_t*)&S[buf][0][r + 8][quad * 2 + 8];
            al[mf][0] = *(uint32_t*)&S[buf][1][r][quad * 2];
            al[mf][1] = *(uint32_t*)&S[buf][1][r + 8][quad * 2];
            al[mf][2] = *(uint32_t*)&S[buf][1][r][quad * 2 + 8];
            al[mf][3] = *(uint32_t*)&S[buf][1][r + 8][quad * 2 + 8];
        }
#pragma unroll
        for (int nf = 0; nf < 8; nf++) {
            const int n = nwarp + nf * 8 + grp;
            bh[nf][0] = *(uint32_t*)&S[buf][2][n][quad * 2];
            bh[nf][1] = *(uint32_t*)&S[buf][2][n][quad * 2 + 8];
            bl[nf][0] = *(uint32_t*)&S[buf][3][n][quad * 2];
            bl[nf][1] = *(uint32_t*)&S[buf][3][n][quad * 2 + 8];
        }
        // ---- 48 MMAs: hi*hi + lo*hi + hi*lo ----
#pragma unroll
        for (int mf = 0; mf < 2; mf++)
#pragma unroll
            for (int nf = 0; nf < 8; nf++) {
                mma16816(acc[mf][nf], ah[mf], bh[nf]);
                mma16816(acc[mf][nf], al[mf], bh[nf]);
                mma16816(acc[mf][nf], ah[mf], bl[nf]);
            }

        if (ch + 1 < DIN / KCH) CP_WAIT0();
        __syncthreads();
        buf ^= 1;
    }

    // ---- writeback ----
#pragma unroll
    for (int mf = 0; mf < 2; mf++) {
        const int r0w = row0 + mwarp + mf * 16 + grp;
        const int r1w = r0w + 8;
#pragma unroll
        for (int nf = 0; nf < 8; nf++) {
            const int col = nwarp + nf * 8 + quad * 2;
            if (r0w < NS)
                *(float2*)(g_fs + (size_t)r0w * HD + col) =
                    make_float2(acc[mf][nf][0], acc[mf][nf][1]);
            if (r1w < NS)
                *(float2*)(g_fs + (size_t)r1w * HD + col) =
                    make_float2(acc[mf][nf][2], acc[mf][nf][3]);
        }
    }
}

// ---------------- K2a: fold v_dst[k][h] = sum_j w_dst[k,h*32+j]*attn[h,j] ---
__global__ void vdst_kernel(const float* __restrict__ wd,
                            const float* __restrict__ attn)
{
    int t = blockIdx.x * blockDim.x + threadIdx.x;
    if (t >= DIN * NH) return;
    int k = t >> 2, h = t & 3;
    float s = 0.0f;
#pragma unroll
    for (int j = 0; j < DH; j++)
        s += wd[(size_t)k * HD + h * DH + j] * attn[h * (2 * DH) + j];
    g_vdst[k * NH + h] = s;
}

// ---------------- K2b: e_dst (round-4 version: conflict-free vs4 access) ----
__global__ __launch_bounds__(256) void edst_kernel(const float* __restrict__ fd)
{
    __shared__ float4 vs4[DIN];
    int tid = threadIdx.x;
    for (int i = tid; i < DIN; i += 256) vs4[i] = *(const float4*)&g_vdst[i * NH];
    __syncthreads();
    int warp = tid >> 5, lane = tid & 31;
    int n = blockIdx.x * 8 + warp;
    if (n >= ND) return;
    const float* fr = fd + (size_t)n * DIN;
    float a0 = 0, a1 = 0, a2 = 0, a3 = 0;
#pragma unroll
    for (int t = 0; t < 8; t++) {
        int k = lane + 32 * t;
        float f = fr[k];
        float4 v = vs4[k];
        a0 += f * v.x; a1 += f * v.y; a2 += f * v.z; a3 += f * v.w;
    }
#pragma unroll
    for (int o = 16; o >= 1; o >>= 1) {
        a0 += __shfl_down_sync(0xffffffffu, a0, o);
        a1 += __shfl_down_sync(0xffffffffu, a1, o);
        a2 += __shfl_down_sync(0xffffffffu, a2, o);
        a3 += __shfl_down_sync(0xffffffffu, a3, o);
    }
    if (lane == 0) {
        g_edst[n * NH + 0] = a0;
        g_edst[n * NH + 1] = a1;
        g_edst[n * NH + 2] = a2;
        g_edst[n * NH + 3] = a3;
    }
}

// ---------------- K2c: e_src from fs (warp per node) ------------------------
__global__ __launch_bounds__(256) void esrc_kernel(const float* __restrict__ attn)
{
    int tid = threadIdx.x;
    int warp = tid >> 5, lane = tid & 31;
    int n = blockIdx.x * 8 + warp;
    if (n >= NS) return;
    int h = lane >> 3;
    int j = (lane & 7) * 4;
    float4 f = *(const float4*)&g_fs[(size_t)n * HD + lane * 4];
    const float* ar = attn + h * (2 * DH) + DH + j;
    float p = f.x * ar[0] + f.y * ar[1] + f.z * ar[2] + f.w * ar[3];
    p += __shfl_down_sync(0xffffffffu, p, 4, 8);
    p += __shfl_down_sync(0xffffffffu, p, 2, 8);
    p += __shfl_down_sync(0xffffffffu, p, 1, 8);
    if ((lane & 7) == 0) g_esrc[n * NH + h] = p;
}

// ---------------- K3: edge logits + leaky relu + dst histogram --------------
__global__ void edge_logits_kernel(const int* __restrict__ src,
                                   const int* __restrict__ dst)
{
    int i = blockIdx.x * blockDim.x + threadIdx.x;
    if (i >= NE) return;
    int s = src[i], d = dst[i];
    float4 es = *(const float4*)&g_esrc[(size_t)s * NH];
    float4 ed = *(const float4*)&g_edst[(size_t)d * NH];
    float4 e;
    e.x = es.x + ed.x; e.x = e.x > 0.f ? e.x : NEG_SLOPE * e.x;
    e.y = es.y + ed.y; e.y = e.y > 0.f ? e.y : NEG_SLOPE * e.y;
    e.z = es.z + ed.z; e.z = e.z > 0.f ? e.z : NEG_SLOPE * e.z;
    e.w = es.w + ed.w; e.w = e.w > 0.f ? e.w : NEG_SLOPE * e.w;
    *(float4*)&g_e[(size_t)i * NH] = e;
    atomicAdd(&g_cnt[d], 1);
}

// ---------------- K4a: per-block exclusive scan of g_cnt --------------------
__global__ __launch_bounds__(256) void scan_block_kernel()
{
    int t = threadIdx.x;
    int i = blockIdx.x * 256 + t;
    int c = (i < ND) ? g_cnt[i] : 0;
    int lane = t & 31, w = t >> 5;
    int inc = c;
#pragma unroll
    for (int o = 1; o < 32; o <<= 1) {
        int n = __shfl_up_sync(0xffffffffu, inc, o);
        if (lane >= o) inc += n;
    }
    __shared__ int ws[8];
    if (lane == 31) ws[w] = inc;
    __syncthreads();
    if (t < 8) {
        int v = ws[t];
        int inc2 = v;
#pragma unroll
        for (int o = 1; o < 8; o <<= 1) {
            int n = __shfl_up_sync(0x000000ffu, inc2, o);
            if (t >= o) inc2 += n;
        }
        ws[t] = inc2 - v;
    }
    __syncthreads();
    int excl = inc - c + ws[w];
    if (i < ND) g_base[i] = excl;
    if (t == 255) g_bsum[blockIdx.x] = excl + c;
}

// ---------------- K4b: scan the 391 block sums ------------------------------
__global__ __launch_bounds__(512) void scan_top_kernel()
{
    int t = threadIdx.x;
    int c = (t < NBLK) ? g_bsum[t] : 0;
    int lane = t & 31, w = t >> 5;
    int inc = c;
#pragma unroll
    for (int o = 1; o < 32; o <<= 1) {
        int n = __shfl_up_sync(0xffffffffu, inc, o);
        if (lane >= o) inc += n;
    }
    __shared__ int ws[16];
    if (lane == 31) ws[w] = inc;
    __syncthreads();
    if (t < 16) {
        int v = ws[t];
        int inc2 = v;
#pragma unroll
        for (int o = 1; o < 16; o <<= 1) {
            int n = __shfl_up_sync(0x0000ffffu, inc2, o);
            if (t >= o) inc2 += n;
        }
        ws[t] = inc2 - v;
    }
    __syncthreads();
    if (t < NBLK) g_boff[t] = inc - c + ws[w];
}

// ---------------- K5: scatter edges into dst-sorted order -------------------
__global__ void scatter_kernel(const int* __restrict__ src,
                               const int* __restrict__ dst)
{
    int i = blockIdx.x * blockDim.x + threadIdx.x;
    if (i >= NE) return;
    int d = dst[i];
    int s = src[i];
    int pos = atomicAdd(&g_wpos[d], 1);
    int slot = g_base[d] + g_boff[d >> 8] + pos;
    g_sorted[slot] = make_int2(i, s);
}

// ---------------- K6: warp-per-dst online-softmax aggregation ---------------
__global__ __launch_bounds__(256) void aggregate_kernel(float* __restrict__ out)
{
    int warp = threadIdx.x >> 5, lane = threadIdx.x & 31;
    int d = blockIdx.x * 8 + warp;
    if (d >= ND) return;
    int base = g_base[d] + g_boff[d >> 8];
    int cnt  = g_cnt[d];
    int h = lane >> 3;

    float m = -CUDART_INF_F;
    float denom = 0.0f;
    float4 acc = make_float4(0.f, 0.f, 0.f, 0.f);

    int2 es; float e; float4 f;
    if (cnt > 0) {
        es = g_sorted[base];
        e  = __ldg(&g_e[(size_t)es.x * NH + h]);
        f  = *(const float4*)&g_fs[(size_t)es.y * HD + lane * 4];
    }
    for (int j = 0; j < cnt; j++) {
        int2 es_n; float e_n; float4 f_n;
        if (j + 1 < cnt) {
            es_n = g_sorted[base + j + 1];
            e_n  = __ldg(&g_e[(size_t)es_n.x * NH + h]);
            f_n  = *(const float4*)&g_fs[(size_t)es_n.y * HD + lane * 4];
        }
        if (e > m) {
            float sc = __expf(m - e);
            m = e;
            denom = denom * sc + 1.0f;
            acc.x = acc.x * sc + f.x;
            acc.y = acc.y * sc + f.y;
            acc.z = acc.z * sc + f.z;
            acc.w = acc.w * sc + f.w;
        } else {
            float w = __expf(e - m);
            denom += w;
            acc.x += w * f.x;
            acc.y += w * f.y;
            acc.z += w * f.z;
            acc.w += w * f.w;
        }
        es = es_n; e = e_n; f = f_n;
    }
    float inv = (cnt > 0) ? 1.0f / denom : 0.0f;
    float4 o;
    o.x = fmaxf(acc.x * inv, 0.f);
    o.y = fmaxf(acc.y * inv, 0.f);
    o.z = fmaxf(acc.z * inv, 0.f);
    o.w = fmaxf(acc.w * inv, 0.f);
    *(float4*)(out + (size_t)d * HD + lane * 4) = o;
}

// ---------------- launch -----------------------------------------------------
extern "C" void kernel_launch(void* const* d_in, const int* in_sizes, int n_in,
                              void* d_out, int out_size)
{
    const float* feat_src = (const float*)d_in[0];
    const float* feat_dst = (const float*)d_in[1];
    const float* w_src    = (const float*)d_in[2];
    const float* w_dst    = (const float*)d_in[3];
    const float* attn     = (const float*)d_in[4];
    const int*   src_idx  = (const int*)d_in[5];
    const int*   dst_idx  = (const int*)d_in[6];
    float* out = (float*)d_out;

    init_kernel<<<(ND + 255) / 256, 256>>>();
    convA_kernel<<<(NS * (DIN / 4) + 255) / 256, 256>>>(feat_src);
    convB_kernel<<<(DIN * HD + 255) / 256, 256>>>(w_src);
    gemm_mma_kernel<<<NSP / 128, 256>>>();
    vdst_kernel<<<(DIN * NH + 255) / 256, 256>>>(w_dst, attn);
    edst_kernel<<<(ND + 7) / 8, 256>>>(feat_dst);
    esrc_kernel<<<(NS + 7) / 8, 256>>>(attn);
    edge_logits_kernel<<<NE / 256, 256>>>(src_idx, dst_idx);
    scan_block_kernel<<<NBLK, 256>>>();
    scan_top_kernel<<<1, 512>>>();
    scatter_kernel<<<NE / 256, 256>>>(src_idx, dst_idx);
    aggregate_kernel<<<(ND + 7) / 8, 256>>>(out);
}

// round 13
// speedup vs baseline: 1.2729x; 1.1479x over previous
#include <cuda_runtime.h>
#include <cuda_bf16.h>
#include <cuda_fp16.h>
#include <math_constants.h>
#include <cstdint>

#define NS 100000
#define ND 100000
#define NE 1600000
#define DIN 256
#define NH 4
#define DH 32
#define HD 128          // NH * DH
#define NEG_SLOPE 0.2f
#define NBLK ((ND + 255) / 256)   // 391 scan blocks
#define NSP 100096                // NS padded to 128 (782 CTAs * 128)

// ---------------- scratch (device globals; no allocs allowed) ----------------
__device__ __align__(16) __half g_fsh[(size_t)NS * HD];  // 25.6 MB fp16 projected feats
__device__ __align__(16) __nv_bfloat16 g_ahi[(size_t)NSP * DIN];  // A split hi
__device__ __align__(16) __nv_bfloat16 g_alo[(size_t)NSP * DIN];  // A split lo
__device__ __align__(16) __nv_bfloat16 g_bhi[HD * DIN];  // w_src hi, n-major [128][256]
__device__ __align__(16) __nv_bfloat16 g_blo[HD * DIN];  // w_src lo, n-major
__device__ __align__(16) float g_esrc[NS * NH];
__device__ __align__(16) float g_edst[ND * NH];
__device__ __align__(16) float g_e[(size_t)NE * NH];     // edge logits (post leaky-relu)
__device__ __align__(16) float g_vdst[DIN * NH];         // folded w_dst @ attn_dst
__device__ int  g_cnt[ND];
__device__ int  g_wpos[ND];
__device__ int  g_base[ND];
__device__ int  g_bsum[NBLK];
__device__ int  g_boff[NBLK];
__device__ __align__(8) int2 g_sorted[NE];   // {edge_id, src} sorted by dst

// ---------------- K0: init counters ----------------
__global__ void init_kernel() {
    int tix = blockIdx.x * blockDim.x + threadIdx.x;
    if (tix < ND) { g_cnt[tix] = 0; g_wpos[tix] = 0; }
}

// ---------------- P1: split A -> bf16 hi/lo ---------------------------------
__global__ __launch_bounds__(256) void convA_kernel(const float* __restrict__ A)
{
    size_t i = (size_t)blockIdx.x * blockDim.x + threadIdx.x;
    if (i >= (size_t)NS * (DIN / 4)) return;
    float4 v = ((const float4*)A)[i];
    __nv_bfloat162 h0 = __floats2bfloat162_rn(v.x, v.y);
    __nv_bfloat162 h1 = __floats2bfloat162_rn(v.z, v.w);
    float2 f0 = __bfloat1622float2(h0);
    float2 f1 = __bfloat1622float2(h1);
    __nv_bfloat162 l0 = __floats2bfloat162_rn(v.x - f0.x, v.y - f0.y);
    __nv_bfloat162 l1 = __floats2bfloat162_rn(v.z - f1.x, v.w - f1.y);
    ((uint2*)g_ahi)[i] = make_uint2(*(uint32_t*)&h0, *(uint32_t*)&h1);
    ((uint2*)g_alo)[i] = make_uint2(*(uint32_t*)&l0, *(uint32_t*)&l1);
}

// ---------------- P2: split B -> bf16 hi/lo, transposed to n-major ----------
__global__ void convB_kernel(const float* __restrict__ B)
{
    int i = blockIdx.x * blockDim.x + threadIdx.x;
    if (i >= DIN * HD) return;
    int k = i >> 7, n = i & 127;
    float v = B[i];
    __nv_bfloat16 h = __float2bfloat16(v);
    __nv_bfloat16 l = __float2bfloat16(v - __bfloat162float(h));
    g_bhi[n * DIN + k] = h;
    g_blo[n * DIN + k] = l;
}

// ---------------- K1: fs = A @ B via mma.sync bf16x3, 2-stage cp.async ------
// (49152 B static smem = exactly the 48KB limit; measured 99.5us in R10)
#define KCH 16
#define SSTR 24      // bf16 stride; 12 words -> conflict-free frag loads
#define NCH (DIN / KCH)

__device__ __forceinline__ void mma16816(float* c, const uint32_t* a, const uint32_t* b) {
    asm volatile("mma.sync.aligned.m16n8k16.row.col.f32.bf16.bf16.f32 "
                 "{%0,%1,%2,%3}, {%4,%5,%6,%7}, {%8,%9}, {%0,%1,%2,%3};"
                 : "+f"(c[0]), "+f"(c[1]), "+f"(c[2]), "+f"(c[3])
                 : "r"(a[0]), "r"(a[1]), "r"(a[2]), "r"(a[3]), "r"(b[0]), "r"(b[1]));
}
__device__ __forceinline__ uint32_t smem_u32(const void* p) {
    uint32_t a;
    asm("{ .reg .u64 t; cvta.to.shared.u64 t, %1; cvt.u32.u64 %0, t; }" : "=r"(a) : "l"(p));
    return a;
}
__device__ __forceinline__ void cpa16(uint32_t dst, const void* src) {
    asm volatile("cp.async.ca.shared.global [%0], [%1], 16;" :: "r"(dst), "l"(src));
}
#define CP_COMMIT() asm volatile("cp.async.commit_group;" ::: "memory")
#define CP_WAIT0()  asm volatile("cp.async.wait_group 0;" ::: "memory")

__global__ __launch_bounds__(256, 2) void gemm_mma_kernel()
{
    // [stage][array: Ahi,Alo,Bhi,Blo][row 0..127][SSTR] = 49152 bytes
    __shared__ __align__(16) __nv_bfloat16 S[2][4][128][SSTR];

    const int tid  = threadIdx.x;
    const int wid  = tid >> 5;
    const int lane = tid & 31;
    const int grp  = lane >> 2;
    const int quad = lane & 3;
    const int mwarp = (wid & 3) * 32;
    const int nwarp = (wid >> 2) * 64;
    const int row0  = blockIdx.x * 128;

    float acc[2][8][4];
#pragma unroll
    for (int mf = 0; mf < 2; mf++)
#pragma unroll
        for (int nf = 0; nf < 8; nf++)
#pragma unroll
            for (int q = 0; q < 4; q++) acc[mf][nf][q] = 0.0f;

    auto copy_chunk = [&](int ch, int stage) {
        const int k0 = ch * KCH;
#pragma unroll
        for (int i = 0; i < 4; i++) {
            int idx = i * 256 + tid;
            int arr = idx >> 8;
            int row = (idx >> 1) & 127;
            int seg = idx & 1;
            const __nv_bfloat16* sp;
            if (arr == 0)      sp = g_ahi + (size_t)(row0 + row) * DIN + k0 + seg * 8;
            else if (arr == 1) sp = g_alo + (size_t)(row0 + row) * DIN + k0 + seg * 8;
            else if (arr == 2) sp = g_bhi + (size_t)row * DIN + k0 + seg * 8;
            else               sp = g_blo + (size_t)row * DIN + k0 + seg * 8;
            cpa16(smem_u32(&S[stage][arr][row][seg * 8]), sp);
        }
    };

    copy_chunk(0, 0);
    CP_COMMIT();
    CP_WAIT0();
    __syncthreads();

    int buf = 0;
    for (int ch = 0; ch < NCH; ch++) {
        if (ch + 1 < NCH) {
            copy_chunk(ch + 1, buf ^ 1);
            CP_COMMIT();
        }

        // ---- fragment loads (conflict-free: 12*grp + quad covers 32 banks) ----
        uint32_t ah[2][4], al[2][4], bh[8][2], bl[8][2];
#pragma unroll
        for (int mf = 0; mf < 2; mf++) {
            const int r = mwarp + mf * 16 + grp;
            ah[mf][0] = *(uint32_t*)&S[buf][0][r][quad * 2];
            ah[mf][1] = *(uint32_t*)&S[buf][0][r + 8][quad * 2];
            ah[mf][2] = *(uint32_t*)&S[buf][0][r][quad * 2 + 8];
            ah[mf][3] = *(uint32_t*)&S[buf][0][r + 8][quad * 2 + 8];
            al[mf][0] = *(uint32_t*)&S[buf][1][r][quad * 2];
            al[mf][1] = *(uint32_t*)&S[buf][1][r + 8][quad * 2];
            al[mf][2] = *(uint32_t*)&S[buf][1][r][quad * 2 + 8];
            al[mf][3] = *(uint32_t*)&S[buf][1][r + 8][quad * 2 + 8];
        }
#pragma unroll
        for (int nf = 0; nf < 8; nf++) {
            const int n = nwarp + nf * 8 + grp;
            bh[nf][0] = *(uint32_t*)&S[buf][2][n][quad * 2];
            bh[nf][1] = *(uint32_t*)&S[buf][2][n][quad * 2 + 8];
            bl[nf][0] = *(uint32_t*)&S[buf][3][n][quad * 2];
            bl[nf][1] = *(uint32_t*)&S[buf][3][n][quad * 2 + 8];
        }
        // ---- 48 MMAs: hi*hi + lo*hi + hi*lo ----
#pragma unroll
        for (int mf = 0; mf < 2; mf++)
#pragma unroll
            for (int nf = 0; nf < 8; nf++) {
                mma16816(acc[mf][nf], ah[mf], bh[nf]);
                mma16816(acc[mf][nf], al[mf], bh[nf]);
                mma16816(acc[mf][nf], ah[mf], bl[nf]);
            }

        if (ch + 1 < NCH) CP_WAIT0();
        __syncthreads();
        buf ^= 1;
    }

    // ---- writeback (fp16) ----
#pragma unroll
    for (int mf = 0; mf < 2; mf++) {
        const int r0w = row0 + mwarp + mf * 16 + grp;
        const int r1w = r0w + 8;
#pragma unroll
        for (int nf = 0; nf < 8; nf++) {
            const int col = nwarp + nf * 8 + quad * 2;
            if (r0w < NS)
                *(__half2*)(g_fsh + (size_t)r0w * HD + col) =
                    __floats2half2_rn(acc[mf][nf][0], acc[mf][nf][1]);
            if (r1w < NS)
                *(__half2*)(g_fsh + (size_t)r1w * HD + col) =
                    __floats2half2_rn(acc[mf][nf][2], acc[mf][nf][3]);
        }
    }
}

// ---------------- K2a: fold v_dst[k][h] = sum_j w_dst[k,h*32+j]*attn[h,j] ---
__global__ void vdst_kernel(const float* __restrict__ wd,
                            const float* __restrict__ attn)
{
    int t = blockIdx.x * blockDim.x + threadIdx.x;
    if (t >= DIN * NH) return;
    int k = t >> 2, h = t & 3;
    float s = 0.0f;
#pragma unroll
    for (int j = 0; j < DH; j++)
        s += wd[(size_t)k * HD + h * DH + j] * attn[h * (2 * DH) + j];
    g_vdst[k * NH + h] = s;
}

// ---------------- K2b: e_dst (conflict-free vs4 access) ---------------------
__global__ __launch_bounds__(256) void edst_kernel(const float* __restrict__ fd)
{
    __shared__ float4 vs4[DIN];
    int tid = threadIdx.x;
    for (int i = tid; i < DIN; i += 256) vs4[i] = *(const float4*)&g_vdst[i * NH];
    __syncthreads();
    int warp = tid >> 5, lane = tid & 31;
    int n = blockIdx.x * 8 + warp;
    if (n >= ND) return;
    const float* fr = fd + (size_t)n * DIN;
    float a0 = 0, a1 = 0, a2 = 0, a3 = 0;
#pragma unroll
    for (int t = 0; t < 8; t++) {
        int k = lane + 32 * t;
        float f = fr[k];
        float4 v = vs4[k];
        a0 += f * v.x; a1 += f * v.y; a2 += f * v.z; a3 += f * v.w;
    }
#pragma unroll
    for (int o = 16; o >= 1; o >>= 1) {
        a0 += __shfl_down_sync(0xffffffffu, a0, o);
        a1 += __shfl_down_sync(0xffffffffu, a1, o);
        a2 += __shfl_down_sync(0xffffffffu, a2, o);
        a3 += __shfl_down_sync(0xffffffffu, a3, o);
    }
    if (lane == 0) {
        g_edst[n * NH + 0] = a0;
        g_edst[n * NH + 1] = a1;
        g_edst[n * NH + 2] = a2;
        g_edst[n * NH + 3] = a3;
    }
}

// ---------------- K2c: e_src from fp16 fs (warp per node) -------------------
__global__ __launch_bounds__(256) void esrc_kernel(const float* __restrict__ attn)
{
    int tid = threadIdx.x;
    int warp = tid >> 5, lane = tid & 31;
    int n = blockIdx.x * 8 + warp;
    if (n >= NS) return;
    int h = lane >> 3;
    int j = (lane & 7) * 4;
    uint2 u = *(const uint2*)&g_fsh[(size_t)n * HD + lane * 4];
    float2 f0 = __half22float2(*(__half2*)&u.x);
    float2 f1 = __half22float2(*(__half2*)&u.y);
    const float* ar = attn + h * (2 * DH) + DH + j;
    float p = f0.x * ar[0] + f0.y * ar[1] + f1.x * ar[2] + f1.y * ar[3];
    p += __shfl_down_sync(0xffffffffu, p, 4, 8);
    p += __shfl_down_sync(0xffffffffu, p, 2, 8);
    p += __shfl_down_sync(0xffffffffu, p, 1, 8);
    if ((lane & 7) == 0) g_esrc[n * NH + h] = p;
}

// ---------------- K3: edge logits + leaky relu + dst histogram --------------
__global__ void edge_logits_kernel(const int* __restrict__ src,
                                   const int* __restrict__ dst)
{
    int i = blockIdx.x * blockDim.x + threadIdx.x;
    if (i >= NE) return;
    int s = src[i], d = dst[i];
    float4 es = *(const float4*)&g_esrc[(size_t)s * NH];
    float4 ed = *(const float4*)&g_edst[(size_t)d * NH];
    float4 e;
    e.x = es.x + ed.x; e.x = e.x > 0.f ? e.x : NEG_SLOPE * e.x;
    e.y = es.y + ed.y; e.y = e.y > 0.f ? e.y : NEG_SLOPE * e.y;
    e.z = es.z + ed.z; e.z = e.z > 0.f ? e.z : NEG_SLOPE * e.z;
    e.w = es.w + ed.w; e.w = e.w > 0.f ? e.w : NEG_SLOPE * e.w;
    *(float4*)&g_e[(size_t)i * NH] = e;
    atomicAdd(&g_cnt[d], 1);
}

// ---------------- K4a: per-block exclusive scan of g_cnt --------------------
__global__ __launch_bounds__(256) void scan_block_kernel()
{
    int t = threadIdx.x;
    int i = blockIdx.x * 256 + t;
    int c = (i < ND) ? g_cnt[i] : 0;
    int lane = t & 31, w = t >> 5;
    int inc = c;
#pragma unroll
    for (int o = 1; o < 32; o <<= 1) {
        int n = __shfl_up_sync(0xffffffffu, inc, o);
        if (lane >= o) inc += n;
    }
    __shared__ int ws[8];
    if (lane == 31) ws[w] = inc;
    __syncthreads();
    if (t < 8) {
        int v = ws[t];
        int inc2 = v;
#pragma unroll
        for (int o = 1; o < 8; o <<= 1) {
            int n = __shfl_up_sync(0x000000ffu, inc2, o);
            if (t >= o) inc2 += n;
        }
        ws[t] = inc2 - v;
    }
    __syncthreads();
    int excl = inc - c + ws[w];
    if (i < ND) g_base[i] = excl;
    if (t == 255) g_bsum[blockIdx.x] = excl + c;
}

// ---------------- K4b: scan the 391 block sums ------------------------------
__global__ __launch_bounds__(512) void scan_top_kernel()
{
    int t = threadIdx.x;
    int c = (t < NBLK) ? g_bsum[t] : 0;
    int lane = t & 31, w = t >> 5;
    int inc = c;
#pragma unroll
    for (int o = 1; o < 32; o <<= 1) {
        int n = __shfl_up_sync(0xffffffffu, inc, o);
        if (lane >= o) inc += n;
    }
    __shared__ int ws[16];
    if (lane == 31) ws[w] = inc;
    __syncthreads();
    if (t < 16) {
        int v = ws[t];
        int inc2 = v;
#pragma unroll
        for (int o = 1; o < 16; o <<= 1) {
            int n = __shfl_up_sync(0x0000ffffu, inc2, o);
            if (t >= o) inc2 += n;
        }
        ws[t] = inc2 - v;
    }
    __syncthreads();
    if (t < NBLK) g_boff[t] = inc - c + ws[w];
}

// ---------------- K5: scatter edges into dst-sorted order -------------------
__global__ void scatter_kernel(const int* __restrict__ src,
                               const int* __restrict__ dst)
{
    int i = blockIdx.x * blockDim.x + threadIdx.x;
    if (i >= NE) return;
    int d = dst[i];
    int s = src[i];
    int pos = atomicAdd(&g_wpos[d], 1);
    int slot = g_base[d] + g_boff[d >> 8] + pos;
    g_sorted[slot] = make_int2(i, s);
}

// ---------------- K6: warp-per-dst online-softmax aggregation (fp16 fs) -----
__global__ __launch_bounds__(256) void aggregate_kernel(float* __restrict__ out)
{
    int warp = threadIdx.x >> 5, lane = threadIdx.x & 31;
    int d = blockIdx.x * 8 + warp;
    if (d >= ND) return;
    int base = g_base[d] + g_boff[d >> 8];
    int cnt  = g_cnt[d];
    int h = lane >> 3;

    float m = -CUDART_INF_F;
    float denom = 0.0f;
    float4 acc = make_float4(0.f, 0.f, 0.f, 0.f);

    int2 es; float e; uint2 fu;
    if (cnt > 0) {
        es = g_sorted[base];
        e  = __ldg(&g_e[(size_t)es.x * NH + h]);
        fu = *(const uint2*)&g_fsh[(size_t)es.y * HD + lane * 4];
    }
    for (int j = 0; j < cnt; j++) {
        int2 es_n; float e_n; uint2 fu_n;
        if (j + 1 < cnt) {
            es_n = g_sorted[base + j + 1];
            e_n  = __ldg(&g_e[(size_t)es_n.x * NH + h]);
            fu_n = *(const uint2*)&g_fsh[(size_t)es_n.y * HD + lane * 4];
        }
        float2 f0 = __half22float2(*(__half2*)&fu.x);
        float2 f1 = __half22float2(*(__half2*)&fu.y);
        if (e > m) {
            float sc = __expf(m - e);
            m = e;
            denom = denom * sc + 1.0f;
            acc.x = acc.x * sc + f0.x;
            acc.y = acc.y * sc + f0.y;
            acc.z = acc.z * sc + f1.x;
            acc.w = acc.w * sc + f1.y;
        } else {
            float w = __expf(e - m);
            denom += w;
            acc.x += w * f0.x;
            acc.y += w * f0.y;
            acc.z += w * f1.x;
            acc.w += w * f1.y;
        }
        es = es_n; e = e_n; fu = fu_n;
    }
    float inv = (cnt > 0) ? 1.0f / denom : 0.0f;
    float4 o;
    o.x = fmaxf(acc.x * inv, 0.f);
    o.y = fmaxf(acc.y * inv, 0.f);
    o.z = fmaxf(acc.z * inv, 0.f);
    o.w = fmaxf(acc.w * inv, 0.f);
    *(float4*)(out + (size_t)d * HD + lane * 4) = o;
}

// ---------------- launch -----------------------------------------------------
extern "C" void kernel_launch(void* const* d_in, const int* in_sizes, int n_in,
                              void* d_out, int out_size)
{
    const float* feat_src = (const float*)d_in[0];
    const float* feat_dst = (const float*)d_in[1];
    const float* w_src    = (const float*)d_in[2];
    const float* w_dst    = (const float*)d_in[3];
    const float* attn     = (const float*)d_in[4];
    const int*   src_idx  = (const int*)d_in[5];
    const int*   dst_idx  = (const int*)d_in[6];
    float* out = (float*)d_out;

    init_kernel<<<(ND + 255) / 256, 256>>>();
    convA_kernel<<<(NS * (DIN / 4) + 255) / 256, 256>>>(feat_src);
    convB_kernel<<<(DIN * HD + 255) / 256, 256>>>(w_src);
    gemm_mma_kernel<<<NSP / 128, 256>>>();
    vdst_kernel<<<(DIN * NH + 255) / 256, 256>>>(w_dst, attn);
    edst_kernel<<<(ND + 7) / 8, 256>>>(feat_dst);
    esrc_kernel<<<(NS + 7) / 8, 256>>>(attn);
    edge_logits_kernel<<<NE / 256, 256>>>(src_idx, dst_idx);
    scan_block_kernel<<<NBLK, 256>>>();
    scan_top_kernel<<<1, 512>>>();
    scatter_kernel<<<NE / 256, 256>>>(src_idx, dst_idx);
    aggregate_kernel<<<(ND + 7) / 8, 256>>>(out);
}

// round 14
// speedup vs baseline: 1.2807x; 1.0062x over previous
#include <cuda_runtime.h>
#include <cuda_bf16.h>
#include <cuda_fp16.h>
#include <math_constants.h>
#include <cstdint>

#define NS 100000
#define ND 100000
#define NE 1600000
#define DIN 256
#define NH 4
#define DH 32
#define HD 128          // NH * DH
#define NEG_SLOPE 0.2f
#define NBLK ((ND + 255) / 256)   // 391 scan blocks
#define NSP 100096                // NS padded to 128 (782 CTAs * 128)

// ---------------- scratch (device globals; no allocs allowed) ----------------
__device__ __align__(16) __half g_fsh[(size_t)NS * HD];  // 25.6 MB fp16 projected feats
__device__ __align__(16) __nv_bfloat16 g_ahi[(size_t)NSP * DIN];  // A split hi
__device__ __align__(16) __nv_bfloat16 g_alo[(size_t)NSP * DIN];  // A split lo
__device__ __align__(16) __nv_bfloat16 g_bhi[HD * DIN];  // w_src hi, n-major [128][256]
__device__ __align__(16) __nv_bfloat16 g_blo[HD * DIN];  // w_src lo, n-major
__device__ __align__(16) float g_esrc[NS * NH];
__device__ __align__(16) float g_edst[ND * NH];
__device__ __align__(16) float g_vdst[DIN * NH];         // folded w_dst @ attn_dst
__device__ int  g_cnt[ND];
__device__ int  g_wpos[ND];
__device__ int  g_base[ND];
__device__ int  g_bsum[NBLK];
__device__ int  g_boff[NBLK];
__device__ int  g_ssrc[NE];       // src id per dst-sorted slot

// ---------------- K0: init counters ----------------
__global__ void init_kernel() {
    int tix = blockIdx.x * blockDim.x + threadIdx.x;
    if (tix < ND) { g_cnt[tix] = 0; g_wpos[tix] = 0; }
}

// ---------------- P1: split A -> bf16 hi/lo ---------------------------------
__global__ __launch_bounds__(256) void convA_kernel(const float* __restrict__ A)
{
    size_t i = (size_t)blockIdx.x * blockDim.x + threadIdx.x;
    if (i >= (size_t)NS * (DIN / 4)) return;
    float4 v = ((const float4*)A)[i];
    __nv_bfloat162 h0 = __floats2bfloat162_rn(v.x, v.y);
    __nv_bfloat162 h1 = __floats2bfloat162_rn(v.z, v.w);
    float2 f0 = __bfloat1622float2(h0);
    float2 f1 = __bfloat1622float2(h1);
    __nv_bfloat162 l0 = __floats2bfloat162_rn(v.x - f0.x, v.y - f0.y);
    __nv_bfloat162 l1 = __floats2bfloat162_rn(v.z - f1.x, v.w - f1.y);
    ((uint2*)g_ahi)[i] = make_uint2(*(uint32_t*)&h0, *(uint32_t*)&h1);
    ((uint2*)g_alo)[i] = make_uint2(*(uint32_t*)&l0, *(uint32_t*)&l1);
}

// ---------------- P2: split B -> bf16 hi/lo, transposed to n-major ----------
__global__ void convB_kernel(const float* __restrict__ B)
{
    int i = blockIdx.x * blockDim.x + threadIdx.x;
    if (i >= DIN * HD) return;
    int k = i >> 7, n = i & 127;
    float v = B[i];
    __nv_bfloat16 h = __float2bfloat16(v);
    __nv_bfloat16 l = __float2bfloat16(v - __bfloat162float(h));
    g_bhi[n * DIN + k] = h;
    g_blo[n * DIN + k] = l;
}

// ---------------- K1: fs = A @ B via mma.sync bf16x3, 2-stage cp.async ------
// (frozen: measured 99.5/99.6us; 49152 B static smem = 48KB limit)
#define KCH 16
#define SSTR 24
#define NCH (DIN / KCH)

__device__ __forceinline__ void mma16816(float* c, const uint32_t* a, const uint32_t* b) {
    asm volatile("mma.sync.aligned.m16n8k16.row.col.f32.bf16.bf16.f32 "
                 "{%0,%1,%2,%3}, {%4,%5,%6,%7}, {%8,%9}, {%0,%1,%2,%3};"
                 : "+f"(c[0]), "+f"(c[1]), "+f"(c[2]), "+f"(c[3])
                 : "r"(a[0]), "r"(a[1]), "r"(a[2]), "r"(a[3]), "r"(b[0]), "r"(b[1]));
}
__device__ __forceinline__ uint32_t smem_u32(const void* p) {
    uint32_t a;
    asm("{ .reg .u64 t; cvta.to.shared.u64 t, %1; cvt.u32.u64 %0, t; }" : "=r"(a) : "l"(p));
    return a;
}
__device__ __forceinline__ void cpa16(uint32_t dst, const void* src) {
    asm volatile("cp.async.ca.shared.global [%0], [%1], 16;" :: "r"(dst), "l"(src));
}
#define CP_COMMIT() asm volatile("cp.async.commit_group;" ::: "memory")
#define CP_WAIT0()  asm volatile("cp.async.wait_group 0;" ::: "memory")

__global__ __launch_bounds__(256, 2) void gemm_mma_kernel()
{
    __shared__ __align__(16) __nv_bfloat16 S[2][4][128][SSTR];

    const int tid  = threadIdx.x;
    const int wid  = tid >> 5;
    const int lane = tid & 31;
    const int grp  = lane >> 2;
    const int quad = lane & 3;
    const int mwarp = (wid & 3) * 32;
    const int nwarp = (wid >> 2) * 64;
    const int row0  = blockIdx.x * 128;

    float acc[2][8][4];
#pragma unroll
    for (int mf = 0; mf < 2; mf++)
#pragma unroll
        for (int nf = 0; nf < 8; nf++)
#pragma unroll
            for (int q = 0; q < 4; q++) acc[mf][nf][q] = 0.0f;

    auto copy_chunk = [&](int ch, int stage) {
        const int k0 = ch * KCH;
#pragma unroll
        for (int i = 0; i < 4; i++) {
            int idx = i * 256 + tid;
            int arr = idx >> 8;
            int row = (idx >> 1) & 127;
            int seg = idx & 1;
            const __nv_bfloat16* sp;
            if (arr == 0)      sp = g_ahi + (size_t)(row0 + row) * DIN + k0 + seg * 8;
            else if (arr == 1) sp = g_alo + (size_t)(row0 + row) * DIN + k0 + seg * 8;
            else if (arr == 2) sp = g_bhi + (size_t)row * DIN + k0 + seg * 8;
            else               sp = g_blo + (size_t)row * DIN + k0 + seg * 8;
            cpa16(smem_u32(&S[stage][arr][row][seg * 8]), sp);
        }
    };

    copy_chunk(0, 0);
    CP_COMMIT();
    CP_WAIT0();
    __syncthreads();

    int buf = 0;
    for (int ch = 0; ch < NCH; ch++) {
        if (ch + 1 < NCH) {
            copy_chunk(ch + 1, buf ^ 1);
            CP_COMMIT();
        }

        uint32_t ah[2][4], al[2][4], bh[8][2], bl[8][2];
#pragma unroll
        for (int mf = 0; mf < 2; mf++) {
            const int r = mwarp + mf * 16 + grp;
            ah[mf][0] = *(uint32_t*)&S[buf][0][r][quad * 2];
            ah[mf][1] = *(uint32_t*)&S[buf][0][r + 8][quad * 2];
            ah[mf][2] = *(uint32_t*)&S[buf][0][r][quad * 2 + 8];
            ah[mf][3] = *(uint32_t*)&S[buf][0][r + 8][quad * 2 + 8];
            al[mf][0] = *(uint32_t*)&S[buf][1][r][quad * 2];
            al[mf][1] = *(uint32_t*)&S[buf][1][r + 8][quad * 2];
            al[mf][2] = *(uint32_t*)&S[buf][1][r][quad * 2 + 8];
            al[mf][3] = *(uint32_t*)&S[buf][1][r + 8][quad * 2 + 8];
        }
#pragma unroll
        for (int nf = 0; nf < 8; nf++) {
            const int n = nwarp + nf * 8 + grp;
            bh[nf][0] = *(uint32_t*)&S[buf][2][n][quad * 2];
            bh[nf][1] = *(uint32_t*)&S[buf][2][n][quad * 2 + 8];
            bl[nf][0] = *(uint32_t*)&S[buf][3][n][quad * 2];
            bl[nf][1] = *(uint32_t*)&S[buf][3][n][quad * 2 + 8];
        }
#pragma unroll
        for (int mf = 0; mf < 2; mf++)
#pragma unroll
            for (int nf = 0; nf < 8; nf++) {
                mma16816(acc[mf][nf], ah[mf], bh[nf]);
                mma16816(acc[mf][nf], al[mf], bh[nf]);
                mma16816(acc[mf][nf], ah[mf], bl[nf]);
            }

        if (ch + 1 < NCH) CP_WAIT0();
        __syncthreads();
        buf ^= 1;
    }

    // ---- writeback (fp16) ----
#pragma unroll
    for (int mf = 0; mf < 2; mf++) {
        const int r0w = row0 + mwarp + mf * 16 + grp;
        const int r1w = r0w + 8;
#pragma unroll
        for (int nf = 0; nf < 8; nf++) {
            const int col = nwarp + nf * 8 + quad * 2;
            if (r0w < NS)
                *(__half2*)(g_fsh + (size_t)r0w * HD + col) =
                    __floats2half2_rn(acc[mf][nf][0], acc[mf][nf][1]);
            if (r1w < NS)
                *(__half2*)(g_fsh + (size_t)r1w * HD + col) =
                    __floats2half2_rn(acc[mf][nf][2], acc[mf][nf][3]);
        }
    }
}

// ---------------- K2a: fold v_dst[k][h] = sum_j w_dst[k,h*32+j]*attn[h,j] ---
__global__ void vdst_kernel(const float* __restrict__ wd,
                            const float* __restrict__ attn)
{
    int t = blockIdx.x * blockDim.x + threadIdx.x;
    if (t >= DIN * NH) return;
    int k = t >> 2, h = t & 3;
    float s = 0.0f;
#pragma unroll
    for (int j = 0; j < DH; j++)
        s += wd[(size_t)k * HD + h * DH + j] * attn[h * (2 * DH) + j];
    g_vdst[k * NH + h] = s;
}

// ---------------- K2b: e_dst, float4 global loads + padded smem -------------
// vsd[h][k + (k>>5)]: for fixed j, lanes hit banks {4l+j, 4l+j+1, 4l+j+2,
// 4l+j+3} over the four lane-octets -> all 32 banks distinct (conflict-free).
__global__ __launch_bounds__(256) void edst_kernel(const float* __restrict__ fd)
{
    __shared__ float vsd[NH][DIN + 8];   // 264 floats per head
    int tid = threadIdx.x;
    for (int i = tid; i < DIN * NH; i += 256) {
        int k = i >> 2, h = i & 3;
        vsd[h][k + (k >> 5)] = g_vdst[i];
    }
    __syncthreads();
    int warp = tid >> 5, lane = tid & 31;
    int n = blockIdx.x * 8 + warp;
    if (n >= ND) return;
    const float4* fr4 = (const float4*)(fd + (size_t)n * DIN);
    float4 x = fr4[lane];          // k = 4*lane + j
    float4 y = fr4[lane + 32];     // k = 128 + 4*lane + j
    float fx[8] = {x.x, x.y, x.z, x.w, y.x, y.y, y.z, y.w};
    float a0 = 0, a1 = 0, a2 = 0, a3 = 0;
#pragma unroll
    for (int j = 0; j < 8; j++) {
        int k = (j < 4) ? (4 * lane + j) : (128 + 4 * lane + (j - 4));
        int idx = k + (k >> 5);
        a0 += fx[j] * vsd[0][idx];
        a1 += fx[j] * vsd[1][idx];
        a2 += fx[j] * vsd[2][idx];
        a3 += fx[j] * vsd[3][idx];
    }
#pragma unroll
    for (int o = 16; o >= 1; o >>= 1) {
        a0 += __shfl_down_sync(0xffffffffu, a0, o);
        a1 += __shfl_down_sync(0xffffffffu, a1, o);
        a2 += __shfl_down_sync(0xffffffffu, a2, o);
        a3 += __shfl_down_sync(0xffffffffu, a3, o);
    }
    if (lane == 0) {
        g_edst[n * NH + 0] = a0;
        g_edst[n * NH + 1] = a1;
        g_edst[n * NH + 2] = a2;
        g_edst[n * NH + 3] = a3;
    }
}

// ---------------- K2c: e_src from fp16 fs (warp per node) -------------------
__global__ __launch_bounds__(256) void esrc_kernel(const float* __restrict__ attn)
{
    int tid = threadIdx.x;
    int warp = tid >> 5, lane = tid & 31;
    int n = blockIdx.x * 8 + warp;
    if (n >= NS) return;
    int h = lane >> 3;
    int j = (lane & 7) * 4;
    uint2 u = *(const uint2*)&g_fsh[(size_t)n * HD + lane * 4];
    float2 f0 = __half22float2(*(__half2*)&u.x);
    float2 f1 = __half22float2(*(__half2*)&u.y);
    const float* ar = attn + h * (2 * DH) + DH + j;
    float p = f0.x * ar[0] + f0.y * ar[1] + f1.x * ar[2] + f1.y * ar[3];
    p += __shfl_down_sync(0xffffffffu, p, 4, 8);
    p += __shfl_down_sync(0xffffffffu, p, 2, 8);
    p += __shfl_down_sync(0xffffffffu, p, 1, 8);
    if ((lane & 7) == 0) g_esrc[n * NH + h] = p;
}

// ---------------- K3: dst histogram only ------------------------------------
__global__ void hist_kernel(const int* __restrict__ dst)
{
    int i = blockIdx.x * blockDim.x + threadIdx.x;
    if (i >= NE) return;
    atomicAdd(&g_cnt[dst[i]], 1);
}

// ---------------- K4a: per-block exclusive scan of g_cnt --------------------
__global__ __launch_bounds__(256) void scan_block_kernel()
{
    int t = threadIdx.x;
    int i = blockIdx.x * 256 + t;
    int c = (i < ND) ? g_cnt[i] : 0;
    int lane = t & 31, w = t >> 5;
    int inc = c;
#pragma unroll
    for (int o = 1; o < 32; o <<= 1) {
        int n = __shfl_up_sync(0xffffffffu, inc, o);
        if (lane >= o) inc += n;
    }
    __shared__ int ws[8];
    if (lane == 31) ws[w] = inc;
    __syncthreads();
    if (t < 8) {
        int v = ws[t];
        int inc2 = v;
#pragma unroll
        for (int o = 1; o < 8; o <<= 1) {
            int n = __shfl_up_sync(0x000000ffu, inc2, o);
            if (t >= o) inc2 += n;
        }
        ws[t] = inc2 - v;
    }
    __syncthreads();
    int excl = inc - c + ws[w];
    if (i < ND) g_base[i] = excl;
    if (t == 255) g_bsum[blockIdx.x] = excl + c;
}

// ---------------- K4b: scan the 391 block sums ------------------------------
__global__ __launch_bounds__(512) void scan_top_kernel()
{
    int t = threadIdx.x;
    int c = (t < NBLK) ? g_bsum[t] : 0;
    int lane = t & 31, w = t >> 5;
    int inc = c;
#pragma unroll
    for (int o = 1; o < 32; o <<= 1) {
        int n = __shfl_up_sync(0xffffffffu, inc, o);
        if (lane >= o) inc += n;
    }
    __shared__ int ws[16];
    if (lane == 31) ws[w] = inc;
    __syncthreads();
    if (t < 16) {
        int v = ws[t];
        int inc2 = v;
#pragma unroll
        for (int o = 1; o < 16; o <<= 1) {
            int n = __shfl_up_sync(0x0000ffffu, inc2, o);
            if (t >= o) inc2 += n;
        }
        ws[t] = inc2 - v;
    }
    __syncthreads();
    if (t < NBLK) g_boff[t] = inc - c + ws[w];
}

// ---------------- K5: scatter src ids into dst-sorted order -----------------
__global__ void scatter_kernel(const int* __restrict__ src,
                               const int* __restrict__ dst)
{
    int i = blockIdx.x * blockDim.x + threadIdx.x;
    if (i >= NE) return;
    int d = dst[i];
    int s = src[i];
    int pos = atomicAdd(&g_wpos[d], 1);
    g_ssrc[g_base[d] + g_boff[d >> 8] + pos] = s;
}

// ---------------- K6: aggregation with on-the-fly logits --------------------
__global__ __launch_bounds__(256) void aggregate_kernel(float* __restrict__ out)
{
    int warp = threadIdx.x >> 5, lane = threadIdx.x & 31;
    int d = blockIdx.x * 8 + warp;
    if (d >= ND) return;
    int base = g_base[d] + g_boff[d >> 8];
    int cnt  = g_cnt[d];
    int h = lane >> 3;
    float ed = __ldg(&g_edst[(size_t)d * NH + h]);

    float m = -CUDART_INF_F;
    float denom = 0.0f;
    float4 acc = make_float4(0.f, 0.f, 0.f, 0.f);

    float e; uint2 fu;
    if (cnt > 0) {
        int s = g_ssrc[base];
        float es = __ldg(&g_esrc[(size_t)s * NH + h]);
        e = es + ed; e = e > 0.f ? e : NEG_SLOPE * e;
        fu = *(const uint2*)&g_fsh[(size_t)s * HD + lane * 4];
    }
    for (int j = 0; j < cnt; j++) {
        float e_n; uint2 fu_n;
        if (j + 1 < cnt) {
            int s_n = g_ssrc[base + j + 1];
            float es = __ldg(&g_esrc[(size_t)s_n * NH + h]);
            e_n = es + ed; e_n = e_n > 0.f ? e_n : NEG_SLOPE * e_n;
            fu_n = *(const uint2*)&g_fsh[(size_t)s_n * HD + lane * 4];
        }
        float2 f0 = __half22float2(*(__half2*)&fu.x);
        float2 f1 = __half22float2(*(__half2*)&fu.y);
        if (e > m) {
            float sc = __expf(m - e);
            m = e;
            denom = denom * sc + 1.0f;
            acc.x = acc.x * sc + f0.x;
            acc.y = acc.y * sc + f0.y;
            acc.z = acc.z * sc + f1.x;
            acc.w = acc.w * sc + f1.y;
        } else {
            float w = __expf(e - m);
            denom += w;
            acc.x += w * f0.x;
            acc.y += w * f0.y;
            acc.z += w * f1.x;
            acc.w += w * f1.y;
        }
        e = e_n; fu = fu_n;
    }
    float inv = (cnt > 0) ? 1.0f / denom : 0.0f;
    float4 o;
    o.x = fmaxf(acc.x * inv, 0.f);
    o.y = fmaxf(acc.y * inv, 0.f);
    o.z = fmaxf(acc.z * inv, 0.f);
    o.w = fmaxf(acc.w * inv, 0.f);
    *(float4*)(out + (size_t)d * HD + lane * 4) = o;
}

// ---------------- launch -----------------------------------------------------
extern "C" void kernel_launch(void* const* d_in, const int* in_sizes, int n_in,
                              void* d_out, int out_size)
{
    const float* feat_src = (const float*)d_in[0];
    const float* feat_dst = (const float*)d_in[1];
    const float* w_src    = (const float*)d_in[2];
    const float* w_dst    = (const float*)d_in[3];
    const float* attn     = (const float*)d_in[4];
    const int*   src_idx  = (const int*)d_in[5];
    const int*   dst_idx  = (const int*)d_in[6];
    float* out = (float*)d_out;

    init_kernel<<<(ND + 255) / 256, 256>>>();
    convA_kernel<<<(NS * (DIN / 4) + 255) / 256, 256>>>(feat_src);
    convB_kernel<<<(DIN * HD + 255) / 256, 256>>>(w_src);
    gemm_mma_kernel<<<NSP / 128, 256>>>();
    vdst_kernel<<<(DIN * NH + 255) / 256, 256>>>(w_dst, attn);
    edst_kernel<<<(ND + 7) / 8, 256>>>(feat_dst);
    esrc_kernel<<<(NS + 7) / 8, 256>>>(attn);
    hist_kernel<<<NE / 256, 256>>>(dst_idx);
    scan_block_kernel<<<NBLK, 256>>>();
    scan_top_kernel<<<1, 512>>>();
    scatter_kernel<<<NE / 256, 256>>>(src_idx, dst_idx);
    aggregate_kernel<<<(ND + 7) / 8, 256>>>(out);
}

// round 15
// speedup vs baseline: 1.3311x; 1.0393x over previous
#include <cuda_runtime.h>
#include <cuda_bf16.h>
#include <cuda_fp16.h>
#include <math_constants.h>
#include <cstdint>

#define NS 100000
#define ND 100000
#define NE 1600000
#define DIN 256
#define NH 4
#define DH 32
#define HD 128          // NH * DH
#define NEG_SLOPE 0.2f
#define NBLK ((ND + 255) / 256)   // 391 scan blocks
#define NSP 100096                // NS padded to 128 (782 CTAs * 128)

// ---------------- scratch (device globals; no allocs allowed) ----------------
__device__ __align__(16) __half g_fsh[(size_t)NS * HD];  // 25.6 MB fp16 projected feats
__device__ __align__(16) __nv_bfloat16 g_ahi[(size_t)NSP * DIN];  // A split hi
__device__ __align__(16) __nv_bfloat16 g_alo[(size_t)NSP * DIN];  // A split lo
__device__ __align__(16) __nv_bfloat16 g_bhi[HD * DIN];  // w_src hi, n-major [128][256]
__device__ __align__(16) __nv_bfloat16 g_blo[HD * DIN];  // w_src lo, n-major
__device__ __align__(16) float g_esrc[NS * NH];
__device__ __align__(16) float g_edst[ND * NH];
__device__ __align__(16) float g_vdst[DIN * NH];         // folded w_dst @ attn_dst
__device__ int  g_cnt[ND];
__device__ int  g_wpos[ND];
__device__ int  g_base[ND];
__device__ int  g_bsum[NBLK];
__device__ int  g_boff[NBLK];
__device__ int  g_ssrc[NE];       // src id per dst-sorted slot

// ---------------- K0: init counters ----------------
__global__ void init_kernel() {
    int tix = blockIdx.x * blockDim.x + threadIdx.x;
    if (tix < ND) { g_cnt[tix] = 0; g_wpos[tix] = 0; }
}

// ---------------- P1: split A -> bf16 hi/lo ---------------------------------
__global__ __launch_bounds__(256) void convA_kernel(const float* __restrict__ A)
{
    size_t i = (size_t)blockIdx.x * blockDim.x + threadIdx.x;
    if (i >= (size_t)NS * (DIN / 4)) return;
    float4 v = ((const float4*)A)[i];
    __nv_bfloat162 h0 = __floats2bfloat162_rn(v.x, v.y);
    __nv_bfloat162 h1 = __floats2bfloat162_rn(v.z, v.w);
    float2 f0 = __bfloat1622float2(h0);
    float2 f1 = __bfloat1622float2(h1);
    __nv_bfloat162 l0 = __floats2bfloat162_rn(v.x - f0.x, v.y - f0.y);
    __nv_bfloat162 l1 = __floats2bfloat162_rn(v.z - f1.x, v.w - f1.y);
    ((uint2*)g_ahi)[i] = make_uint2(*(uint32_t*)&h0, *(uint32_t*)&h1);
    ((uint2*)g_alo)[i] = make_uint2(*(uint32_t*)&l0, *(uint32_t*)&l1);
}

// ---------------- P2: split B -> bf16 hi/lo, transposed to n-major ----------
__global__ void convB_kernel(const float* __restrict__ B)
{
    int i = blockIdx.x * blockDim.x + threadIdx.x;
    if (i >= DIN * HD) return;
    int k = i >> 7, n = i & 127;
    float v = B[i];
    __nv_bfloat16 h = __float2bfloat16(v);
    __nv_bfloat16 l = __float2bfloat16(v - __bfloat162float(h));
    g_bhi[n * DIN + k] = h;
    g_blo[n * DIN + k] = l;
}

// ---------------- K1: fs = A @ B via mma.sync bf16x3 + ldmatrix -------------
#define KCH 16
#define SSTR 24      // bf16 stride (48 B): LDSM rows hit banks 12r%32, distinct
#define NCH (DIN / KCH)
#define ARR_STRIDE (128 * SSTR * 2)       // 6144 B
#define STAGE_STRIDE (4 * ARR_STRIDE)     // 24576 B

__device__ __forceinline__ void mma16816(float* c, const uint32_t* a, const uint32_t* b) {
    asm volatile("mma.sync.aligned.m16n8k16.row.col.f32.bf16.bf16.f32 "
                 "{%0,%1,%2,%3}, {%4,%5,%6,%7}, {%8,%9}, {%0,%1,%2,%3};"
                 : "+f"(c[0]), "+f"(c[1]), "+f"(c[2]), "+f"(c[3])
                 : "r"(a[0]), "r"(a[1]), "r"(a[2]), "r"(a[3]), "r"(b[0]), "r"(b[1]));
}
__device__ __forceinline__ void ldsm_x4(uint32_t* r, uint32_t addr) {
    asm volatile("ldmatrix.sync.aligned.m8n8.x4.shared.b16 {%0,%1,%2,%3}, [%4];"
                 : "=r"(r[0]), "=r"(r[1]), "=r"(r[2]), "=r"(r[3]) : "r"(addr));
}
__device__ __forceinline__ uint32_t smem_u32(const void* p) {
    uint32_t a;
    asm("{ .reg .u64 t; cvta.to.shared.u64 t, %1; cvt.u32.u64 %0, t; }" : "=r"(a) : "l"(p));
    return a;
}
__device__ __forceinline__ void cpa16(uint32_t dst, const void* src) {
    asm volatile("cp.async.ca.shared.global [%0], [%1], 16;" :: "r"(dst), "l"(src));
}
#define CP_COMMIT() asm volatile("cp.async.commit_group;" ::: "memory")
#define CP_WAIT0()  asm volatile("cp.async.wait_group 0;" ::: "memory")

__global__ __launch_bounds__(256, 2) void gemm_mma_kernel()
{
    __shared__ __align__(16) __nv_bfloat16 S[2][4][128][SSTR];   // 49152 B

    const int tid  = threadIdx.x;
    const int wid  = tid >> 5;
    const int lane = tid & 31;
    const int grp  = lane >> 2;
    const int quad = lane & 3;
    const int mwarp = (wid & 3) * 32;
    const int nwarp = (wid >> 2) * 64;
    const int row0  = blockIdx.x * 128;

    const uint32_t Sbase = smem_u32(&S[0][0][0][0]);

    // ldmatrix per-lane byte offsets (within one array plane)
    // A x4 (one m16k16 frag): matrix j -> row +(j&1)*8, col-byte +(j>>1)*16
    const uint32_t aoff0 = (uint32_t)((mwarp + ((lane >> 3) & 1) * 8 + (lane & 7)) * (SSTR * 2)
                                      + (lane >> 4) * 16);
    const uint32_t aoff1 = aoff0 + 16 * (SSTR * 2);
    // B x4 (two n8k16 frags, nf pair p): matrix j -> row +(j>>1)*8, col-byte +(j&1)*16
    uint32_t boff[4];
#pragma unroll
    for (int p = 0; p < 4; p++)
        boff[p] = (uint32_t)((nwarp + 16 * p + (lane >> 4) * 8 + (lane & 7)) * (SSTR * 2)
                             + ((lane >> 3) & 1) * 16);

    float acc[2][8][4];
#pragma unroll
    for (int mf = 0; mf < 2; mf++)
#pragma unroll
        for (int nf = 0; nf < 8; nf++)
#pragma unroll
            for (int q = 0; q < 4; q++) acc[mf][nf][q] = 0.0f;

    auto copy_chunk = [&](int ch, int stage) {
        const int k0 = ch * KCH;
#pragma unroll
        for (int i = 0; i < 4; i++) {
            int idx = i * 256 + tid;
            int arr = idx >> 8;
            int row = (idx >> 1) & 127;
            int seg = idx & 1;
            const __nv_bfloat16* sp;
            if (arr == 0)      sp = g_ahi + (size_t)(row0 + row) * DIN + k0 + seg * 8;
            else if (arr == 1) sp = g_alo + (size_t)(row0 + row) * DIN + k0 + seg * 8;
            else if (arr == 2) sp = g_bhi + (size_t)row * DIN + k0 + seg * 8;
            else               sp = g_blo + (size_t)row * DIN + k0 + seg * 8;
            cpa16(smem_u32(&S[stage][arr][row][seg * 8]), sp);
        }
    };

    copy_chunk(0, 0);
    CP_COMMIT();
    CP_WAIT0();
    __syncthreads();

    int buf = 0;
    for (int ch = 0; ch < NCH; ch++) {
        if (ch + 1 < NCH) {
            copy_chunk(ch + 1, buf ^ 1);
            CP_COMMIT();
        }

        const uint32_t sb = Sbase + (uint32_t)buf * STAGE_STRIDE;
        uint32_t ah[2][4], al[2][4], bh[8][2], bl[8][2];
        ldsm_x4(ah[0], sb + 0 * ARR_STRIDE + aoff0);
        ldsm_x4(ah[1], sb + 0 * ARR_STRIDE + aoff1);
        ldsm_x4(al[0], sb + 1 * ARR_STRIDE + aoff0);
        ldsm_x4(al[1], sb + 1 * ARR_STRIDE + aoff1);
#pragma unroll
        for (int p = 0; p < 4; p++) {
            uint32_t t[4];
            ldsm_x4(t, sb + 2 * ARR_STRIDE + boff[p]);
            bh[2 * p][0] = t[0]; bh[2 * p][1] = t[1];
            bh[2 * p + 1][0] = t[2]; bh[2 * p + 1][1] = t[3];
            ldsm_x4(t, sb + 3 * ARR_STRIDE + boff[p]);
            bl[2 * p][0] = t[0]; bl[2 * p][1] = t[1];
            bl[2 * p + 1][0] = t[2]; bl[2 * p + 1][1] = t[3];
        }

#pragma unroll
        for (int mf = 0; mf < 2; mf++)
#pragma unroll
            for (int nf = 0; nf < 8; nf++) {
                mma16816(acc[mf][nf], ah[mf], bh[nf]);
                mma16816(acc[mf][nf], al[mf], bh[nf]);
                mma16816(acc[mf][nf], ah[mf], bl[nf]);
            }

        if (ch + 1 < NCH) CP_WAIT0();
        __syncthreads();
        buf ^= 1;
    }

    // ---- writeback (fp16) ----
#pragma unroll
    for (int mf = 0; mf < 2; mf++) {
        const int r0w = row0 + mwarp + mf * 16 + grp;
        const int r1w = r0w + 8;
#pragma unroll
        for (int nf = 0; nf < 8; nf++) {
            const int col = nwarp + nf * 8 + quad * 2;
            if (r0w < NS)
                *(__half2*)(g_fsh + (size_t)r0w * HD + col) =
                    __floats2half2_rn(acc[mf][nf][0], acc[mf][nf][1]);
            if (r1w < NS)
                *(__half2*)(g_fsh + (size_t)r1w * HD + col) =
                    __floats2half2_rn(acc[mf][nf][2], acc[mf][nf][3]);
        }
    }
}

// ---------------- K2a: fold v_dst[k][h] = sum_j w_dst[k,h*32+j]*attn[h,j] ---
__global__ void vdst_kernel(const float* __restrict__ wd,
                            const float* __restrict__ attn)
{
    int t = blockIdx.x * blockDim.x + threadIdx.x;
    if (t >= DIN * NH) return;
    int k = t >> 2, h = t & 3;
    float s = 0.0f;
#pragma unroll
    for (int j = 0; j < DH; j++)
        s += wd[(size_t)k * HD + h * DH + j] * attn[h * (2 * DH) + j];
    g_vdst[k * NH + h] = s;
}

// ---------------- K2b: e_dst, float4 global loads + padded smem -------------
__global__ __launch_bounds__(256) void edst_kernel(const float* __restrict__ fd)
{
    __shared__ float vsd[NH][DIN + 8];
    int tid = threadIdx.x;
    for (int i = tid; i < DIN * NH; i += 256) {
        int k = i >> 2, h = i & 3;
        vsd[h][k + (k >> 5)] = g_vdst[i];
    }
    __syncthreads();
    int warp = tid >> 5, lane = tid & 31;
    int n = blockIdx.x * 8 + warp;
    if (n >= ND) return;
    const float4* fr4 = (const float4*)(fd + (size_t)n * DIN);
    float4 x = fr4[lane];
    float4 y = fr4[lane + 32];
    float fx[8] = {x.x, x.y, x.z, x.w, y.x, y.y, y.z, y.w};
    float a0 = 0, a1 = 0, a2 = 0, a3 = 0;
#pragma unroll
    for (int j = 0; j < 8; j++) {
        int k = (j < 4) ? (4 * lane + j) : (128 + 4 * lane + (j - 4));
        int idx = k + (k >> 5);
        a0 += fx[j] * vsd[0][idx];
        a1 += fx[j] * vsd[1][idx];
        a2 += fx[j] * vsd[2][idx];
        a3 += fx[j] * vsd[3][idx];
    }
#pragma unroll
    for (int o = 16; o >= 1; o >>= 1) {
        a0 += __shfl_down_sync(0xffffffffu, a0, o);
        a1 += __shfl_down_sync(0xffffffffu, a1, o);
        a2 += __shfl_down_sync(0xffffffffu, a2, o);
        a3 += __shfl_down_sync(0xffffffffu, a3, o);
    }
    if (lane == 0) {
        g_edst[n * NH + 0] = a0;
        g_edst[n * NH + 1] = a1;
        g_edst[n * NH + 2] = a2;
        g_edst[n * NH + 3] = a3;
    }
}

// ---------------- K2c: e_src from fp16 fs (warp per node) -------------------
__global__ __launch_bounds__(256) void esrc_kernel(const float* __restrict__ attn)
{
    int tid = threadIdx.x;
    int warp = tid >> 5, lane = tid & 31;
    int n = blockIdx.x * 8 + warp;
    if (n >= NS) return;
    int h = lane >> 3;
    int j = (lane & 7) * 4;
    uint2 u = *(const uint2*)&g_fsh[(size_t)n * HD + lane * 4];
    float2 f0 = __half22float2(*(__half2*)&u.x);
    float2 f1 = __half22float2(*(__half2*)&u.y);
    const float* ar = attn + h * (2 * DH) + DH + j;
    float p = f0.x * ar[0] + f0.y * ar[1] + f1.x * ar[2] + f1.y * ar[3];
    p += __shfl_down_sync(0xffffffffu, p, 4, 8);
    p += __shfl_down_sync(0xffffffffu, p, 2, 8);
    p += __shfl_down_sync(0xffffffffu, p, 1, 8);
    if ((lane & 7) == 0) g_esrc[n * NH + h] = p;
}

// ---------------- K3: dst histogram only ------------------------------------
__global__ void hist_kernel(const int* __restrict__ dst)
{
    int i = blockIdx.x * blockDim.x + threadIdx.x;
    if (i >= NE) return;
    atomicAdd(&g_cnt[dst[i]], 1);
}

// ---------------- K4a: per-block exclusive scan of g_cnt --------------------
__global__ __launch_bounds__(256) void scan_block_kernel()
{
    int t = threadIdx.x;
    int i = blockIdx.x * 256 + t;
    int c = (i < ND) ? g_cnt[i] : 0;
    int lane = t & 31, w = t >> 5;
    int inc = c;
#pragma unroll
    for (int o = 1; o < 32; o <<= 1) {
        int n = __shfl_up_sync(0xffffffffu, inc, o);
        if (lane >= o) inc += n;
    }
    __shared__ int ws[8];
    if (lane == 31) ws[w] = inc;
    __syncthreads();
    if (t < 8) {
        int v = ws[t];
        int inc2 = v;
#pragma unroll
        for (int o = 1; o < 8; o <<= 1) {
            int n = __shfl_up_sync(0x000000ffu, inc2, o);
            if (t >= o) inc2 += n;
        }
        ws[t] = inc2 - v;
    }
    __syncthreads();
    int excl = inc - c + ws[w];
    if (i < ND) g_base[i] = excl;
    if (t == 255) g_bsum[blockIdx.x] = excl + c;
}

// ---------------- K4b: scan the 391 block sums ------------------------------
__global__ __launch_bounds__(512) void scan_top_kernel()
{
    int t = threadIdx.x;
    int c = (t < NBLK) ? g_bsum[t] : 0;
    int lane = t & 31, w = t >> 5;
    int inc = c;
#pragma unroll
    for (int o = 1; o < 32; o <<= 1) {
        int n = __shfl_up_sync(0xffffffffu, inc, o);
        if (lane >= o) inc += n;
    }
    __shared__ int ws[16];
    if (lane == 31) ws[w] = inc;
    __syncthreads();
    if (t < 16) {
        int v = ws[t];
        int inc2 = v;
#pragma unroll
        for (int o = 1; o < 16; o <<= 1) {
            int n = __shfl_up_sync(0x0000ffffu, inc2, o);
            if (t >= o) inc2 += n;
        }
        ws[t] = inc2 - v;
    }
    __syncthreads();
    if (t < NBLK) g_boff[t] = inc - c + ws[w];
}

// ---------------- K5: scatter src ids into dst-sorted order -----------------
__global__ void scatter_kernel(const int* __restrict__ src,
                               const int* __restrict__ dst)
{
    int i = blockIdx.x * blockDim.x + threadIdx.x;
    if (i >= NE) return;
    int d = dst[i];
    int s = src[i];
    int pos = atomicAdd(&g_wpos[d], 1);
    g_ssrc[g_base[d] + g_boff[d >> 8] + pos] = s;
}

// ---------------- K6: aggregation with on-the-fly logits --------------------
__global__ __launch_bounds__(256) void aggregate_kernel(float* __restrict__ out)
{
    int warp = threadIdx.x >> 5, lane = threadIdx.x & 31;
    int d = blockIdx.x * 8 + warp;
    if (d >= ND) return;
    int base = g_base[d] + g_boff[d >> 8];
    int cnt  = g_cnt[d];
    int h = lane >> 3;
    float ed = __ldg(&g_edst[(size_t)d * NH + h]);

    float m = -CUDART_INF_F;
    float denom = 0.0f;
    float4 acc = make_float4(0.f, 0.f, 0.f, 0.f);

    float e; uint2 fu;
    if (cnt > 0) {
        int s = g_ssrc[base];
        float es = __ldg(&g_esrc[(size_t)s * NH + h]);
        e = es + ed; e = e > 0.f ? e : NEG_SLOPE * e;
        fu = *(const uint2*)&g_fsh[(size_t)s * HD + lane * 4];
    }
    for (int j = 0; j < cnt; j++) {
        float e_n; uint2 fu_n;
        if (j + 1 < cnt) {
            int s_n = g_ssrc[base + j + 1];
            float es = __ldg(&g_esrc[(size_t)s_n * NH + h]);
            e_n = es + ed; e_n = e_n > 0.f ? e_n : NEG_SLOPE * e_n;
            fu_n = *(const uint2*)&g_fsh[(size_t)s_n * HD + lane * 4];
        }
        float2 f0 = __half22float2(*(__half2*)&fu.x);
        float2 f1 = __half22float2(*(__half2*)&fu.y);
        if (e > m) {
            float sc = __expf(m - e);
            m = e;
            denom = denom * sc + 1.0f;
            acc.x = acc.x * sc + f0.x;
            acc.y = acc.y * sc + f0.y;
            acc.z = acc.z * sc + f1.x;
            acc.w = acc.w * sc + f1.y;
        } else {
            float w = __expf(e - m);
            denom += w;
            acc.x += w * f0.x;
            acc.y += w * f0.y;
            acc.z += w * f1.x;
            acc.w += w * f1.y;
        }
        e = e_n; fu = fu_n;
    }
    float inv = (cnt > 0) ? 1.0f / denom : 0.0f;
    float4 o;
    o.x = fmaxf(acc.x * inv, 0.f);
    o.y = fmaxf(acc.y * inv, 0.f);
    o.z = fmaxf(acc.z * inv, 0.f);
    o.w = fmaxf(acc.w * inv, 0.f);
    *(float4*)(out + (size_t)d * HD + lane * 4) = o;
}

// ---------------- launch -----------------------------------------------------
extern "C" void kernel_launch(void* const* d_in, const int* in_sizes, int n_in,
                              void* d_out, int out_size)
{
    const float* feat_src = (const float*)d_in[0];
    const float* feat_dst = (const float*)d_in[1];
    const float* w_src    = (const float*)d_in[2];
    const float* w_dst    = (const float*)d_in[3];
    const float* attn     = (const float*)d_in[4];
    const int*   src_idx  = (const int*)d_in[5];
    const int*   dst_idx  = (const int*)d_in[6];
    float* out = (float*)d_out;

    init_kernel<<<(ND + 255) / 256, 256>>>();
    convA_kernel<<<(NS * (DIN / 4) + 255) / 256, 256>>>(feat_src);
    convB_kernel<<<(DIN * HD + 255) / 256, 256>>>(w_src);
    gemm_mma_kernel<<<NSP / 128, 256>>>();
    vdst_kernel<<<(DIN * NH + 255) / 256, 256>>>(w_dst, attn);
    edst_kernel<<<(ND + 7) / 8, 256>>>(feat_dst);
    esrc_kernel<<<(NS + 7) / 8, 256>>>(attn);
    hist_kernel<<<NE / 256, 256>>>(dst_idx);
    scan_block_kernel<<<NBLK, 256>>>();
    scan_top_kernel<<<1, 512>>>();
    scatter_kernel<<<NE / 256, 256>>>(src_idx, dst_idx);
    aggregate_kernel<<<(ND + 7) / 8, 256>>>(out);
}